// round 13
// baseline (speedup 1.0000x reference)
#include <cuda_runtime.h>
#include <cuda_bf16.h>
#include <math.h>
#include <stdint.h>
#include <stddef.h>

// Problem dims (fixed by reference)
constexpr int Bn  = 2;
constexpr int Sn  = 2048;
constexpr int Dn  = 512;
constexpr int Hn  = 8;
constexpr int DKn = 64;
constexpr int DFFn= 2048;
constexpr int BSn = Bn * Sn;          // 4096 token rows
constexpr int QKVN = 3 * Dn;          // 1536 fused qkv width
constexpr int BHn = Bn * Hn;          // 16 batched heads

// ---------------- scratch (device globals; no allocation allowed) ----------
__device__ float g_x1  [BSn * Dn];
__device__ float g_t2  [BSn * Dn];
__device__ float g_rowsum[BHn * Sn];
// activation bf16 hi/lo planes
__device__ __nv_bfloat16 g_x_h  [BSn * Dn],   g_x_l  [BSn * Dn];
__device__ __nv_bfloat16 g_qkv_h[BSn * QKVN], g_qkv_l[BSn * QKVN];
__device__ __nv_bfloat16 g_ctx_h[BSn * Dn],   g_ctx_l[BSn * Dn];
__device__ __nv_bfloat16 g_x1_h [BSn * Dn],   g_x1_l [BSn * Dn];
__device__ __nv_bfloat16 g_ff_h [BSn * DFFn], g_ff_l [BSn * DFFn];
// weight bf16 hi/lo planes (K-major, [N,K])
__device__ __nv_bfloat16 g_wqkv_h[QKVN * Dn], g_wqkv_l[QKVN * Dn];
__device__ __nv_bfloat16 g_wo_h  [Dn * Dn],   g_wo_l  [Dn * Dn];
__device__ __nv_bfloat16 g_w1_h  [DFFn * Dn], g_w1_l  [DFFn * Dn];
__device__ __nv_bfloat16 g_w2_h  [Dn * DFFn], g_w2_l  [Dn * DFFn];
// V transposed per (b,h): [bh][64][Sn] bf16 hi/lo
__device__ __nv_bfloat16 g_vt_h[BHn * DKn * Sn], g_vt_l[BHn * DKn * Sn];

// ============================ PTX helpers ==================================
__device__ __forceinline__ uint32_t smem_u32(const void* p) {
    uint32_t a;
    asm("{ .reg .u64 t; cvta.to.shared.u64 t, %1; cvt.u32.u64 %0, t; }"
        : "=r"(a) : "l"(p));
    return a;
}
__device__ __forceinline__ void mma_bf16(float* c, const uint32_t* a, const uint32_t* b) {
    asm volatile("mma.sync.aligned.m16n8k16.row.col.f32.bf16.bf16.f32 "
        "{%0,%1,%2,%3}, {%4,%5,%6,%7}, {%8,%9}, {%0,%1,%2,%3};"
        : "+f"(c[0]), "+f"(c[1]), "+f"(c[2]), "+f"(c[3])
        : "r"(a[0]), "r"(a[1]), "r"(a[2]), "r"(a[3]), "r"(b[0]), "r"(b[1]));
}
__device__ __forceinline__ void ldsm4(uint32_t* r, uint32_t addr) {
    asm volatile("ldmatrix.sync.aligned.m8n8.x4.shared.b16 {%0,%1,%2,%3}, [%4];"
        : "=r"(r[0]), "=r"(r[1]), "=r"(r[2]), "=r"(r[3]) : "r"(addr));
}
__device__ __forceinline__ uint32_t pk(__nv_bfloat16 a, __nv_bfloat16 b) {
    return (uint32_t)__bfloat16_as_ushort(a) | ((uint32_t)__bfloat16_as_ushort(b) << 16);
}
__device__ __forceinline__ void split2(float x, float y, uint32_t& hw, uint32_t& lw) {
    __nv_bfloat16 h0 = __float2bfloat16_rn(x);
    __nv_bfloat16 h1 = __float2bfloat16_rn(y);
    hw = pk(h0, h1);
    lw = pk(__float2bfloat16_rn(x - __bfloat162float(h0)),
            __float2bfloat16_rn(y - __bfloat162float(h1)));
}
__device__ __forceinline__ void cpa16(uint32_t dst, const void* src) {
    asm volatile("cp.async.cg.shared.global [%0], [%1], 16;" :: "r"(dst), "l"(src));
}
__device__ __forceinline__ void cpa_commit() {
    asm volatile("cp.async.commit_group;" ::: "memory");
}
template<int N> __device__ __forceinline__ void cpa_wait() {
    asm volatile("cp.async.wait_group %0;" :: "n"(N) : "memory");
}

// ================= shared tiling constants =================================
constexpr int KC      = 32;
constexpr int AST     = 20;                 // padded b32 words per 32-elt row
constexpr int PLANE_W = 128 * AST;          // 2560 words
constexpr int STAGE_W = 4 * PLANE_W;        // Ah, Al, Bh, Bl
constexpr int GEMM_SMEM = 2 * STAGE_W * 4;  // 81920 B

// ldmatrix lane-address constants (within a warp):
//  A x4 tiles: (m0-7,k0-7)(m8-15,k0-7)(m0-7,k8-15)(m8-15,k8-15)
//  B x4 tiles for nt pair: (n0-7,k0-7)(n0-7,k8-15)(n8-15,k0-7)(n8-15,k8-15)
struct LdsmIdx { int rA, kA, rB, kB; };
__device__ __forceinline__ LdsmIdx ldsm_idx(int lane) {
    LdsmIdx ix;
    int l7 = lane & 7;
    ix.rA = l7 + ((lane & 8)  ? 8 : 0);
    ix.kA = (lane & 16) ? 4 : 0;
    ix.rB = l7 + ((lane & 16) ? 8 : 0);
    ix.kB = (lane & 8)  ? 4 : 0;
    return ix;
}

// ================= dense GEMM: pre-split bf16 planes, cp.async =============
// C = A @ Bt^T. A planes [M,K] row-major, Bt planes [N,K] K-major.
// 128x128 CTA tile, 8 warps of 64x32, KC=32, cp.async double buffer.
// EPI: 0 none, 1 +bias, 2 +bias+gelu.  WF: write fp32 C.  WP: write C planes.
template<int EPI, bool WF, bool WP>
__global__ __launch_bounds__(256)
void gemm_mma(const __nv_bfloat16* __restrict__ Ah_, const __nv_bfloat16* __restrict__ Al_,
              const __nv_bfloat16* __restrict__ Bth, const __nv_bfloat16* __restrict__ Btl,
              const float* __restrict__ bias, float* __restrict__ Cf,
              __nv_bfloat16* __restrict__ Ch, __nv_bfloat16* __restrict__ Cl,
              int M, int N, int K)
{
    extern __shared__ uint32_t smw[];
    const uint32_t sbase = smem_u32(smw);
    const int tid  = threadIdx.x;
    const int wid  = tid >> 5, lane = tid & 31;
    const int grp  = lane >> 2, q = lane & 3;
    const int wr   = wid >> 2, wc = wid & 3;
    const int row0 = blockIdx.y * 128;
    const int col0 = blockIdx.x * 128;
    const LdsmIdx ix = ldsm_idx(lane);

    float c[4][4][4];
    #pragma unroll
    for (int mt = 0; mt < 4; mt++)
        #pragma unroll
        for (int nt = 0; nt < 4; nt++)
            #pragma unroll
            for (int e = 0; e < 4; e++) c[mt][nt][e] = 0.f;

    const int T = K / KC;

    auto issue = [&](int i) {
        int k0 = i * KC;
        uint32_t sb = sbase + (uint32_t)((i & 1) * STAGE_W) * 4;
        #pragma unroll
        for (int it = 0; it < 8; it++) {
            int idx = tid + it * 256;
            int plane = idx >> 9, rem = idx & 511;
            int r = rem >> 2, ch = rem & 3;
            const __nv_bfloat16* src;
            if (plane == 0)      src = Ah_ + (size_t)(row0 + r) * K + k0 + ch * 8;
            else if (plane == 1) src = Al_ + (size_t)(row0 + r) * K + k0 + ch * 8;
            else if (plane == 2) src = Bth + (size_t)(col0 + r) * K + k0 + ch * 8;
            else                 src = Btl + (size_t)(col0 + r) * K + k0 + ch * 8;
            cpa16(sb + (uint32_t)(plane * PLANE_W + r * AST + ch * 4) * 4, src);
        }
        cpa_commit();
    };

    issue(0);
    for (int i = 0; i < T; i++) {
        if (i + 1 < T) { issue(i + 1); cpa_wait<1>(); }
        else           { cpa_wait<0>(); }
        __syncthreads();

        uint32_t sb = sbase + (uint32_t)((i & 1) * STAGE_W) * 4;
        #pragma unroll
        for (int k16 = 0; k16 < 2; k16++) {
            const int kw = k16 * 8;
            uint32_t bhf[8], blf[8];                 // b(nt,i) = [nt*2+i]
            #pragma unroll
            for (int j = 0; j < 2; j++) {
                uint32_t boff = (uint32_t)((wc * 32 + j * 16 + ix.rB) * AST + kw + ix.kB) * 4;
                ldsm4(&bhf[j * 4], sb + (uint32_t)(2 * PLANE_W) * 4 + boff);
                ldsm4(&blf[j * 4], sb + (uint32_t)(3 * PLANE_W) * 4 + boff);
            }
            #pragma unroll
            for (int mt = 0; mt < 4; mt++) {
                uint32_t aoff = (uint32_t)((wr * 64 + mt * 16 + ix.rA) * AST + kw + ix.kA) * 4;
                uint32_t ah[4], al[4];
                ldsm4(ah, sb + aoff);
                ldsm4(al, sb + (uint32_t)PLANE_W * 4 + aoff);
                #pragma unroll
                for (int nt = 0; nt < 4; nt++) {
                    mma_bf16(c[mt][nt], ah, &bhf[nt * 2]);
                    mma_bf16(c[mt][nt], ah, &blf[nt * 2]);
                    mma_bf16(c[mt][nt], al, &bhf[nt * 2]);
                }
            }
        }
        __syncthreads();
    }

    #pragma unroll
    for (int mt = 0; mt < 4; mt++) {
        #pragma unroll
        for (int nt = 0; nt < 4; nt++) {
            int col = col0 + wc * 32 + nt * 8 + 2 * q;
            int r0  = row0 + wr * 64 + mt * 16 + grp;
            float2 v0 = make_float2(c[mt][nt][0], c[mt][nt][1]);
            float2 v1 = make_float2(c[mt][nt][2], c[mt][nt][3]);
            if (EPI >= 1) {
                float b0 = bias[col], b1 = bias[col + 1];
                v0.x += b0; v0.y += b1; v1.x += b0; v1.y += b1;
            }
            if (EPI == 2) {
                v0.x = 0.5f * v0.x * (1.0f + erff(v0.x * 0.70710678118654752f));
                v0.y = 0.5f * v0.y * (1.0f + erff(v0.y * 0.70710678118654752f));
                v1.x = 0.5f * v1.x * (1.0f + erff(v1.x * 0.70710678118654752f));
                v1.y = 0.5f * v1.y * (1.0f + erff(v1.y * 0.70710678118654752f));
            }
            if (WF) {
                *(float2*)&Cf[(size_t)r0 * N + col]       = v0;
                *(float2*)&Cf[(size_t)(r0 + 8) * N + col] = v1;
            }
            if (WP) {
                uint32_t hw, lw;
                split2(v0.x, v0.y, hw, lw);
                *(uint32_t*)&Ch[(size_t)r0 * N + col] = hw;
                *(uint32_t*)&Cl[(size_t)r0 * N + col] = lw;
                split2(v1.x, v1.y, hw, lw);
                *(uint32_t*)&Ch[(size_t)(r0 + 8) * N + col] = hw;
                *(uint32_t*)&Cl[(size_t)(r0 + 8) * N + col] = lw;
            }
        }
    }
}

// ================= attention phase A: S = Q K^T /8 + bias, mask, expsum ====
__global__ __launch_bounds__(256)
void attn_score(const __nv_bfloat16* __restrict__ qh, const __nv_bfloat16* __restrict__ ql,
                const float* __restrict__ sw, const int* __restrict__ mask,
                const float* __restrict__ sa, const float* __restrict__ tb,
                float* __restrict__ S_out, float* __restrict__ rowsum)
{
    extern __shared__ uint32_t smw[];
    __shared__ float s_rb[128];
    __shared__ float s_sum[128];
    const uint32_t sbase = smem_u32(smw);
    const int tid  = threadIdx.x;
    const int wid  = tid >> 5, lane = tid & 31;
    const int grp  = lane >> 2, q = lane & 3;
    const int wr   = wid >> 2, wc = wid & 3;
    const int bh = blockIdx.z, b = bh >> 3, h = bh & 7;
    const int row0 = blockIdx.y * 128;
    const int col0 = blockIdx.x * 128;
    const LdsmIdx ix = ldsm_idx(lane);

    const size_t qbase = (size_t)b * Sn * QKVN + h * DKn;        // Q cols
    const size_t kbase = (size_t)b * Sn * QKVN + Dn + h * DKn;   // K cols

    // issue both K-chunks (K=64)
    #pragma unroll
    for (int s = 0; s < 2; s++) {
        int k0 = s * KC;
        uint32_t sb = sbase + (uint32_t)(s * STAGE_W) * 4;
        #pragma unroll
        for (int it = 0; it < 8; it++) {
            int idx = tid + it * 256;
            int plane = idx >> 9, rem = idx & 511;
            int r = rem >> 2, ch = rem & 3;
            const __nv_bfloat16* src;
            if (plane == 0)      src = qh + qbase + (size_t)(row0 + r) * QKVN + k0 + ch * 8;
            else if (plane == 1) src = ql + qbase + (size_t)(row0 + r) * QKVN + k0 + ch * 8;
            else if (plane == 2) src = qh + kbase + (size_t)(col0 + r) * QKVN + k0 + ch * 8;
            else                 src = ql + kbase + (size_t)(col0 + r) * QKVN + k0 + ch * 8;
            cpa16(sb + (uint32_t)(plane * PLANE_W + r * AST + ch * 4) * 4, src);
        }
    }
    cpa_commit();

    if (tid < 128) {
        int row = row0 + tid;
        const float* swp = sw + ((size_t)b * Sn + row) * 4;
        const float* sap = sa + h * 4;
        s_rb[tid] = tb[h] + sap[0]*swp[0] + sap[1]*swp[1]
                          + sap[2]*swp[2] + sap[3]*swp[3];
        s_sum[tid] = 0.f;
    }

    float c[4][4][4];
    #pragma unroll
    for (int mt = 0; mt < 4; mt++)
        #pragma unroll
        for (int nt = 0; nt < 4; nt++)
            #pragma unroll
            for (int e = 0; e < 4; e++) c[mt][nt][e] = 0.f;

    cpa_wait<0>();
    __syncthreads();

    #pragma unroll
    for (int s = 0; s < 2; s++) {
        uint32_t sb = sbase + (uint32_t)(s * STAGE_W) * 4;
        #pragma unroll
        for (int k16 = 0; k16 < 2; k16++) {
            const int kw = k16 * 8;
            uint32_t bhf[8], blf[8];
            #pragma unroll
            for (int j = 0; j < 2; j++) {
                uint32_t boff = (uint32_t)((wc * 32 + j * 16 + ix.rB) * AST + kw + ix.kB) * 4;
                ldsm4(&bhf[j * 4], sb + (uint32_t)(2 * PLANE_W) * 4 + boff);
                ldsm4(&blf[j * 4], sb + (uint32_t)(3 * PLANE_W) * 4 + boff);
            }
            #pragma unroll
            for (int mt = 0; mt < 4; mt++) {
                uint32_t aoff = (uint32_t)((wr * 64 + mt * 16 + ix.rA) * AST + kw + ix.kA) * 4;
                uint32_t ah[4], al[4];
                ldsm4(ah, sb + aoff);
                ldsm4(al, sb + (uint32_t)PLANE_W * 4 + aoff);
                #pragma unroll
                for (int nt = 0; nt < 4; nt++) {
                    mma_bf16(c[mt][nt], ah, &bhf[nt * 2]);
                    mma_bf16(c[mt][nt], ah, &blf[nt * 2]);
                    mma_bf16(c[mt][nt], al, &bhf[nt * 2]);
                }
            }
        }
    }

    float* S = S_out + (size_t)bh * Sn * Sn;
    float psum[4][2];
    #pragma unroll
    for (int mt = 0; mt < 4; mt++) { psum[mt][0] = 0.f; psum[mt][1] = 0.f; }

    #pragma unroll
    for (int mt = 0; mt < 4; mt++) {
        #pragma unroll
        for (int nt = 0; nt < 4; nt++) {
            int col = col0 + wc * 32 + nt * 8 + 2 * q;
            int r0  = row0 + wr * 64 + mt * 16 + grp;
            #pragma unroll
            for (int half = 0; half < 2; half++) {
                int r = r0 + half * 8;
                float2 v = make_float2(c[mt][nt][2*half], c[mt][nt][2*half + 1]);
                float rb = s_rb[r - row0];
                v.x = v.x * 0.125f + rb;
                v.y = v.y * 0.125f + rb;
                int2 m2 = *(const int2*)&mask[(size_t)r * Sn + col];
                if (m2.x == 0) v.x = -1e9f;
                if (m2.y == 0) v.y = -1e9f;
                psum[mt][half] += __expf(v.x) + __expf(v.y);
                *(float2*)&S[(size_t)r * Sn + col] = v;
            }
        }
    }
    // reduce expsum across q lanes, accumulate per-row into smem then gmem
    #pragma unroll
    for (int mt = 0; mt < 4; mt++) {
        #pragma unroll
        for (int half = 0; half < 2; half++) {
            float t = psum[mt][half];
            t += __shfl_xor_sync(0xffffffffu, t, 1);
            t += __shfl_xor_sync(0xffffffffu, t, 2);
            if (q == 0)
                atomicAdd(&s_sum[wr * 64 + mt * 16 + half * 8 + grp], t);
        }
    }
    __syncthreads();
    if (tid < 128)
        atomicAdd(&rowsum[(size_t)bh * Sn + row0 + tid], s_sum[tid]);
}

// ================= attention phase C: p=exp(S)/sum, write P, ctx = P @ V ===
constexpr int PV_APL   = 128 * AST;
constexpr int PV_BPL   = 64 * AST;
constexpr int PV_STAGE = 2 * PV_APL + 2 * PV_BPL;
constexpr int PV_SMEM  = 2 * PV_STAGE * 4;

__global__ __launch_bounds__(256)
void attn_pv(float* __restrict__ Pm, const float* __restrict__ rowsum,
             const __nv_bfloat16* __restrict__ vth, const __nv_bfloat16* __restrict__ vtl,
             __nv_bfloat16* __restrict__ ctxh, __nv_bfloat16* __restrict__ ctxl)
{
    extern __shared__ uint32_t smw[];
    __shared__ float s_inv[128];
    const uint32_t sbase = smem_u32(smw);
    const int tid  = threadIdx.x;
    const int wid  = tid >> 5, lane = tid & 31;
    const int grp  = lane >> 2, q = lane & 3;
    const int bh = blockIdx.y, b = bh >> 3, h = bh & 7;
    const int m0 = blockIdx.x * 128;
    const LdsmIdx ix = ldsm_idx(lane);

    float* A = Pm + (size_t)bh * Sn * Sn;
    const __nv_bfloat16* Bh_ = vth + (size_t)bh * DKn * Sn;
    const __nv_bfloat16* Bl_ = vtl + (size_t)bh * DKn * Sn;

    if (tid < 128) s_inv[tid] = 1.f / rowsum[(size_t)bh * Sn + m0 + tid];
    __syncthreads();

    float c[8][4];
    #pragma unroll
    for (int nt = 0; nt < 8; nt++)
        #pragma unroll
        for (int e = 0; e < 4; e++) c[nt][e] = 0.f;

    const int T = Sn / KC;   // 64
    float4 ra[4]; uint4 rbh, rbl;

    auto stage_A = [&](uint32_t* stg, int k0) {
        #pragma unroll
        for (int it = 0; it < 4; it++) {
            int idx = tid + it * 256;
            int r = idx >> 3, f = idx & 7;
            float4 v = ra[it];
            float inv = s_inv[r];
            v.x = __expf(v.x) * inv; v.y = __expf(v.y) * inv;
            v.z = __expf(v.z) * inv; v.w = __expf(v.w) * inv;
            *(float4*)&A[(size_t)(m0 + r) * Sn + k0 + f * 4] = v;   // final attn
            int w = r * AST + f * 2;
            uint32_t h0, h1, l0, l1;
            split2(v.x, v.y, h0, l0);
            split2(v.z, v.w, h1, l1);
            stg[w] = h0; stg[w + 1] = h1;
            stg[PV_APL + w] = l0; stg[PV_APL + w + 1] = l1;
        }
        int r = tid >> 2, f = tid & 3;
        int w = r * AST + f * 4;
        *(uint4*)&stg[2 * PV_APL + w] = rbh;
        *(uint4*)&stg[2 * PV_APL + PV_BPL + w] = rbl;
    };
    auto ldg_AB = [&](int k0) {
        #pragma unroll
        for (int it = 0; it < 4; it++) {
            int idx = tid + it * 256;
            int r = idx >> 3, f = idx & 7;
            ra[it] = *(const float4*)&A[(size_t)(m0 + r) * Sn + k0 + f * 4];
        }
        int r = tid >> 2, f = tid & 3;
        rbh = *(const uint4*)&Bh_[(size_t)r * Sn + k0 + f * 8];
        rbl = *(const uint4*)&Bl_[(size_t)r * Sn + k0 + f * 8];
    };

    ldg_AB(0);
    stage_A(smw, 0);
    __syncthreads();

    for (int i = 0; i < T; i++) {
        uint32_t sb = sbase + (uint32_t)((i & 1) * PV_STAGE) * 4;

        if (i + 1 < T) ldg_AB((i + 1) * KC);

        #pragma unroll
        for (int k16 = 0; k16 < 2; k16++) {
            const int kw = k16 * 8;
            uint32_t aoff = (uint32_t)((wid * 16 + ix.rA) * AST + kw + ix.kA) * 4;
            uint32_t ah[4], al[4];
            ldsm4(ah, sb + aoff);
            ldsm4(al, sb + (uint32_t)PV_APL * 4 + aoff);
            uint32_t bhf[16], blf[16];
            #pragma unroll
            for (int j = 0; j < 4; j++) {
                uint32_t boff = (uint32_t)((j * 16 + ix.rB) * AST + kw + ix.kB) * 4;
                ldsm4(&bhf[j * 4], sb + (uint32_t)(2 * PV_APL) * 4 + boff);
                ldsm4(&blf[j * 4], sb + (uint32_t)(2 * PV_APL + PV_BPL) * 4 + boff);
            }
            #pragma unroll
            for (int nt = 0; nt < 8; nt++) {
                mma_bf16(c[nt], ah, &bhf[nt * 2]);
                mma_bf16(c[nt], ah, &blf[nt * 2]);
                mma_bf16(c[nt], al, &bhf[nt * 2]);
            }
        }
        __syncthreads();
        if (i + 1 < T) {
            stage_A(smw + ((i + 1) & 1) * PV_STAGE, (i + 1) * KC);
            __syncthreads();
        }
    }

    #pragma unroll
    for (int nt = 0; nt < 8; nt++) {
        int col = h * DKn + nt * 8 + 2 * q;
        int r0  = m0 + wid * 16 + grp;
        uint32_t hw, lw;
        split2(c[nt][0], c[nt][1], hw, lw);
        *(uint32_t*)&ctxh[(size_t)(b * Sn + r0) * Dn + col] = hw;
        *(uint32_t*)&ctxl[(size_t)(b * Sn + r0) * Dn + col] = lw;
        split2(c[nt][2], c[nt][3], hw, lw);
        *(uint32_t*)&ctxh[(size_t)(b * Sn + r0 + 8) * Dn + col] = hw;
        *(uint32_t*)&ctxl[(size_t)(b * Sn + r0 + 8) * Dn + col] = lw;
    }
}

// ============================ small utility kernels ========================
__global__ __launch_bounds__(256)
void zero_f32(float* __restrict__ p, int n)
{
    int i = blockIdx.x * 256 + threadIdx.x;
    if (i < n) p[i] = 0.f;
}

// fp32 -> bf16 hi/lo planes (contiguous)
__global__ __launch_bounds__(256)
void split_planes(const float* __restrict__ src, __nv_bfloat16* __restrict__ h,
                  __nv_bfloat16* __restrict__ l, int n4)
{
    int i = blockIdx.x * 256 + threadIdx.x;
    if (i >= n4) return;
    float4 v = ((const float4*)src)[i];
    uint32_t h0, l0, h1, l1;
    split2(v.x, v.y, h0, l0);
    split2(v.z, v.w, h1, l1);
    ((uint2*)h)[i] = make_uint2(h0, h1);
    ((uint2*)l)[i] = make_uint2(l0, l1);
}

// W[K,N] -> Wt[N,K] bf16 hi/lo planes
__global__ __launch_bounds__(256)
void transpose_w(const float* __restrict__ W, __nv_bfloat16* __restrict__ Wth,
                 __nv_bfloat16* __restrict__ Wtl, int K, int N)
{
    __shared__ float t[32][33];
    int x = blockIdx.x * 32 + threadIdx.x;
    #pragma unroll
    for (int j = 0; j < 4; j++)
        t[threadIdx.y + j * 8][threadIdx.x] =
            W[(size_t)(blockIdx.y * 32 + threadIdx.y + j * 8) * N + x];
    __syncthreads();
    int x2 = blockIdx.y * 32 + threadIdx.x;
    #pragma unroll
    for (int j = 0; j < 4; j++) {
        float v = t[threadIdx.x][threadIdx.y + j * 8];
        __nv_bfloat16 hi = __float2bfloat16_rn(v);
        size_t o = (size_t)(blockIdx.x * 32 + threadIdx.y + j * 8) * K + x2;
        Wth[o] = hi;
        Wtl[o] = __float2bfloat16_rn(v - __bfloat162float(hi));
    }
}

// V slice of qkv planes -> vt[bh][64][Sn] bf16 hi/lo
__global__ __launch_bounds__(256)
void transpose_v(const __nv_bfloat16* __restrict__ qh, const __nv_bfloat16* __restrict__ ql,
                 __nv_bfloat16* __restrict__ vth, __nv_bfloat16* __restrict__ vtl)
{
    __shared__ float t[32][33];
    const int bh = blockIdx.z, b = bh >> 3, h = bh & 7;
    const int s0 = blockIdx.x * 32;
    const int d0 = blockIdx.y * 32;
    const int vcol = 2 * Dn + h * DKn;
    #pragma unroll
    for (int j = 0; j < 4; j++) {
        size_t o = (size_t)(b * Sn + s0 + threadIdx.y + j * 8) * QKVN + vcol + d0 + threadIdx.x;
        t[threadIdx.y + j * 8][threadIdx.x] =
            __bfloat162float(qh[o]) + __bfloat162float(ql[o]);
    }
    __syncthreads();
    #pragma unroll
    for (int j = 0; j < 4; j++) {
        float v = t[threadIdx.x][threadIdx.y + j * 8];
        __nv_bfloat16 hi = __float2bfloat16_rn(v);
        size_t o = ((size_t)bh * DKn + d0 + threadIdx.y + j * 8) * Sn + s0 + threadIdx.x;
        vth[o] = hi;
        vtl[o] = __float2bfloat16_rn(v - __bfloat162float(hi));
    }
}

// ---------------------------------------------------------------------------
// out = LayerNorm(a + r) * g + b   (+ optional bf16 hi/lo planes of out)
// ---------------------------------------------------------------------------
__global__ __launch_bounds__(256)
void add_ln(const float* __restrict__ a, const float* __restrict__ r,
            const float* __restrict__ g, const float* __restrict__ be,
            float* __restrict__ out, __nv_bfloat16* __restrict__ oh,
            __nv_bfloat16* __restrict__ ol)
{
    const int row = blockIdx.x, tid = threadIdx.x;
    const float* ap = a + (size_t)row * Dn;
    const float* rp = r + (size_t)row * Dn;
    float v0 = ap[tid]       + rp[tid];
    float v1 = ap[tid + 256] + rp[tid + 256];

    __shared__ float red[8];
    __shared__ float s_mu, s_inv;
    const int w = tid >> 5, lane = tid & 31;

    float s = v0 + v1;
    #pragma unroll
    for (int o = 16; o > 0; o >>= 1) s += __shfl_xor_sync(0xffffffffu, s, o);
    if (lane == 0) red[w] = s;
    __syncthreads();
    if (tid < 32) {
        float t = (tid < 8) ? red[tid] : 0.f;
        #pragma unroll
        for (int o = 4; o > 0; o >>= 1) t += __shfl_xor_sync(0xffffffffu, t, o);
        if (tid == 0) s_mu = t * (1.f / Dn);
    }
    __syncthreads();
    float mu = s_mu;
    float d0 = v0 - mu, d1 = v1 - mu;

    float qv = d0*d0 + d1*d1;
    #pragma unroll
    for (int o = 16; o > 0; o >>= 1) qv += __shfl_xor_sync(0xffffffffu, qv, o);
    __syncthreads();
    if (lane == 0) red[w] = qv;
    __syncthreads();
    if (tid < 32) {
        float t = (tid < 8) ? red[tid] : 0.f;
        #pragma unroll
        for (int o = 4; o > 0; o >>= 1) t += __shfl_xor_sync(0xffffffffu, t, o);
        if (tid == 0) s_inv = rsqrtf(t * (1.f / Dn) + 1e-6f);
    }
    __syncthreads();
    float inv = s_inv;
    float o0 = d0 * inv * g[tid]       + be[tid];
    float o1 = d1 * inv * g[tid + 256] + be[tid + 256];
    float* op = out + (size_t)row * Dn;
    op[tid]       = o0;
    op[tid + 256] = o1;
    if (oh) {
        __nv_bfloat16 h0 = __float2bfloat16_rn(o0);
        __nv_bfloat16 h1 = __float2bfloat16_rn(o1);
        size_t base = (size_t)row * Dn;
        oh[base + tid]       = h0;
        oh[base + tid + 256] = h1;
        ol[base + tid]       = __float2bfloat16_rn(o0 - __bfloat162float(h0));
        ol[base + tid + 256] = __float2bfloat16_rn(o1 - __bfloat162float(h1));
    }
}

// ---------------------------------------------------------------------------
extern "C" void kernel_launch(void* const* d_in, const int* in_sizes, int n_in,
                              void* d_out, int out_size)
{
    const float* x    = (const float*)d_in[0];
    const float* sw   = (const float*)d_in[1];
    const int*   mask = (const int*)  d_in[2];
    const float* Wq   = (const float*)d_in[3];
    const float* Wk   = (const float*)d_in[4];
    const float* Wv   = (const float*)d_in[5];
    const float* Wo   = (const float*)d_in[6];
    const float* bo   = (const float*)d_in[7];
    const float* sa   = (const float*)d_in[8];
    const float* tb   = (const float*)d_in[9];
    const float* ln1g = (const float*)d_in[10];
    const float* ln1b = (const float*)d_in[11];
    const float* ln2g = (const float*)d_in[12];
    const float* ln2b = (const float*)d_in[13];
    const float* W1   = (const float*)d_in[14];
    const float* b1   = (const float*)d_in[15];
    const float* W2   = (const float*)d_in[16];
    const float* b2   = (const float*)d_in[17];

    float* out_x2   = (float*)d_out;
    float* out_attn = (float*)d_out + (size_t)BSn * Dn;

    float *x1, *t2, *rowsum;
    __nv_bfloat16 *xh, *xl, *qkvh, *qkvl, *ctxh, *ctxl, *x1h, *x1l, *ffh, *ffl;
    __nv_bfloat16 *wqkv_h, *wqkv_l, *wo_h, *wo_l, *w1_h, *w1_l, *w2_h, *w2_l, *vth, *vtl;
    cudaGetSymbolAddress((void**)&x1,     g_x1);
    cudaGetSymbolAddress((void**)&t2,     g_t2);
    cudaGetSymbolAddress((void**)&rowsum, g_rowsum);
    cudaGetSymbolAddress((void**)&xh,     g_x_h);
    cudaGetSymbolAddress((void**)&xl,     g_x_l);
    cudaGetSymbolAddress((void**)&qkvh,   g_qkv_h);
    cudaGetSymbolAddress((void**)&qkvl,   g_qkv_l);
    cudaGetSymbolAddress((void**)&ctxh,   g_ctx_h);
    cudaGetSymbolAddress((void**)&ctxl,   g_ctx_l);
    cudaGetSymbolAddress((void**)&x1h,    g_x1_h);
    cudaGetSymbolAddress((void**)&x1l,    g_x1_l);
    cudaGetSymbolAddress((void**)&ffh,    g_ff_h);
    cudaGetSymbolAddress((void**)&ffl,    g_ff_l);
    cudaGetSymbolAddress((void**)&wqkv_h, g_wqkv_h);
    cudaGetSymbolAddress((void**)&wqkv_l, g_wqkv_l);
    cudaGetSymbolAddress((void**)&wo_h,   g_wo_h);
    cudaGetSymbolAddress((void**)&wo_l,   g_wo_l);
    cudaGetSymbolAddress((void**)&w1_h,   g_w1_h);
    cudaGetSymbolAddress((void**)&w1_l,   g_w1_l);
    cudaGetSymbolAddress((void**)&w2_h,   g_w2_h);
    cudaGetSymbolAddress((void**)&w2_l,   g_w2_l);
    cudaGetSymbolAddress((void**)&vth,    g_vt_h);
    cudaGetSymbolAddress((void**)&vtl,    g_vt_l);

    cudaFuncSetAttribute(gemm_mma<0,false,true>, cudaFuncAttributeMaxDynamicSharedMemorySize, GEMM_SMEM);
    cudaFuncSetAttribute(gemm_mma<1,true,false>, cudaFuncAttributeMaxDynamicSharedMemorySize, GEMM_SMEM);
    cudaFuncSetAttribute(gemm_mma<2,false,true>, cudaFuncAttributeMaxDynamicSharedMemorySize, GEMM_SMEM);
    cudaFuncSetAttribute(attn_score, cudaFuncAttributeMaxDynamicSharedMemorySize, GEMM_SMEM);
    cudaFuncSetAttribute(attn_pv,    cudaFuncAttributeMaxDynamicSharedMemorySize, PV_SMEM);

    dim3 tb8(32, 8);
    dim3 blk(256);

    // weight transposes + input split
    transpose_w<<<dim3(Dn/32,  Dn/32),  tb8>>>(Wq, wqkv_h,            wqkv_l,            Dn, Dn);
    transpose_w<<<dim3(Dn/32,  Dn/32),  tb8>>>(Wk, wqkv_h + Dn*Dn,    wqkv_l + Dn*Dn,    Dn, Dn);
    transpose_w<<<dim3(Dn/32,  Dn/32),  tb8>>>(Wv, wqkv_h + 2*Dn*Dn,  wqkv_l + 2*Dn*Dn,  Dn, Dn);
    transpose_w<<<dim3(Dn/32,  Dn/32),  tb8>>>(Wo, wo_h, wo_l, Dn, Dn);
    transpose_w<<<dim3(DFFn/32, Dn/32), tb8>>>(W1, w1_h, w1_l, Dn, DFFn);
    transpose_w<<<dim3(Dn/32, DFFn/32), tb8>>>(W2, w2_h, w2_l, DFFn, Dn);
    split_planes<<<(BSn*Dn/4 + 255)/256, blk>>>(x, xh, xl, BSn*Dn/4);
    zero_f32<<<(BHn*Sn + 255)/256, blk>>>(rowsum, BHn*Sn);

    // fused QKV projection -> planes
    gemm_mma<0,false,true><<<dim3(QKVN/128, BSn/128), blk, GEMM_SMEM>>>(
        xh, xl, wqkv_h, wqkv_l, nullptr, nullptr, qkvh, qkvl, BSn, QKVN, Dn);

    // V transpose for PV phase
    transpose_v<<<dim3(Sn/32, DKn/32, BHn), tb8>>>(qkvh, qkvl, vth, vtl);

    // attention: raw scores + expsums -> normalize-in-pv (writes final attn)
    attn_score<<<dim3(Sn/128, Sn/128, BHn), blk, GEMM_SMEM>>>(
        qkvh, qkvl, sw, mask, sa, tb, out_attn, rowsum);
    attn_pv<<<dim3(Sn/128, BHn), blk, PV_SMEM>>>(
        out_attn, rowsum, vth, vtl, ctxh, ctxl);

    // output projection + bias
    gemm_mma<1,true,false><<<dim3(Dn/128, BSn/128), blk, GEMM_SMEM>>>(
        ctxh, ctxl, wo_h, wo_l, bo, t2, nullptr, nullptr, BSn, Dn, Dn);
    add_ln<<<BSn, blk>>>(x, t2, ln1g, ln1b, x1, x1h, x1l);

    // FFN
    gemm_mma<2,false,true><<<dim3(DFFn/128, BSn/128), blk, GEMM_SMEM>>>(
        x1h, x1l, w1_h, w1_l, b1, nullptr, ffh, ffl, BSn, DFFn, Dn);
    gemm_mma<1,true,false><<<dim3(Dn/128, BSn/128), blk, GEMM_SMEM>>>(
        ffh, ffl, w2_h, w2_l, b2, t2, nullptr, nullptr, BSn, Dn, DFFn);

    add_ln<<<BSn, blk>>>(x1, t2, ln2g, ln2b, out_x2, nullptr, nullptr);
}

// round 14
// speedup vs baseline: 1.3664x; 1.3664x over previous
#include <cuda_runtime.h>
#include <cuda_bf16.h>
#include <math.h>
#include <stdint.h>
#include <stddef.h>

// Problem dims (fixed by reference)
constexpr int Bn  = 2;
constexpr int Sn  = 2048;
constexpr int Dn  = 512;
constexpr int Hn  = 8;
constexpr int DKn = 64;
constexpr int DFFn= 2048;
constexpr int BSn = Bn * Sn;          // 4096 token rows
constexpr int QKVN = 3 * Dn;          // 1536 fused qkv width
constexpr int BHn = Bn * Hn;          // 16 batched heads

// ---------------- scratch (device globals; no allocation allowed) ----------
__device__ float g_x1  [BSn * Dn];
__device__ float g_t2  [BSn * Dn];
__device__ float g_rowsum[BHn * Sn];
__device__ unsigned char g_mask8[(size_t)Sn * Sn];
// activation bf16 hi/lo planes
__device__ __nv_bfloat16 g_x_h  [BSn * Dn],   g_x_l  [BSn * Dn];
__device__ __nv_bfloat16 g_qkv_h[BSn * QKVN], g_qkv_l[BSn * QKVN];
__device__ __nv_bfloat16 g_ctx_h[BSn * Dn],   g_ctx_l[BSn * Dn];
__device__ __nv_bfloat16 g_x1_h [BSn * Dn],   g_x1_l [BSn * Dn];
__device__ __nv_bfloat16 g_ff_h [BSn * DFFn], g_ff_l [BSn * DFFn];
// weight bf16 hi/lo planes (K-major, [N,K])
__device__ __nv_bfloat16 g_wqkv_h[QKVN * Dn], g_wqkv_l[QKVN * Dn];
__device__ __nv_bfloat16 g_wo_h  [Dn * Dn],   g_wo_l  [Dn * Dn];
__device__ __nv_bfloat16 g_w1_h  [DFFn * Dn], g_w1_l  [DFFn * Dn];
__device__ __nv_bfloat16 g_w2_h  [Dn * DFFn], g_w2_l  [Dn * DFFn];
// V transposed per (b,h): [bh][64][Sn] bf16 hi/lo
__device__ __nv_bfloat16 g_vt_h[BHn * DKn * Sn], g_vt_l[BHn * DKn * Sn];

// ============================ PTX helpers ==================================
__device__ __forceinline__ uint32_t smem_u32(const void* p) {
    uint32_t a;
    asm("{ .reg .u64 t; cvta.to.shared.u64 t, %1; cvt.u32.u64 %0, t; }"
        : "=r"(a) : "l"(p));
    return a;
}
__device__ __forceinline__ void mma_bf16(float* c, const uint32_t* a, const uint32_t* b) {
    asm volatile("mma.sync.aligned.m16n8k16.row.col.f32.bf16.bf16.f32 "
        "{%0,%1,%2,%3}, {%4,%5,%6,%7}, {%8,%9}, {%0,%1,%2,%3};"
        : "+f"(c[0]), "+f"(c[1]), "+f"(c[2]), "+f"(c[3])
        : "r"(a[0]), "r"(a[1]), "r"(a[2]), "r"(a[3]), "r"(b[0]), "r"(b[1]));
}
__device__ __forceinline__ uint32_t pk(__nv_bfloat16 a, __nv_bfloat16 b) {
    return (uint32_t)__bfloat16_as_ushort(a) | ((uint32_t)__bfloat16_as_ushort(b) << 16);
}
__device__ __forceinline__ void split2(float x, float y, uint32_t& hw, uint32_t& lw) {
    __nv_bfloat16 h0 = __float2bfloat16_rn(x);
    __nv_bfloat16 h1 = __float2bfloat16_rn(y);
    hw = pk(h0, h1);
    lw = pk(__float2bfloat16_rn(x - __bfloat162float(h0)),
            __float2bfloat16_rn(y - __bfloat162float(h1)));
}
__device__ __forceinline__ void cpa16(uint32_t dst, const void* src) {
    asm volatile("cp.async.cg.shared.global [%0], [%1], 16;" :: "r"(dst), "l"(src));
}
__device__ __forceinline__ void cpa_commit() {
    asm volatile("cp.async.commit_group;" ::: "memory");
}
template<int N> __device__ __forceinline__ void cpa_wait() {
    asm volatile("cp.async.wait_group %0;" :: "n"(N) : "memory");
}

// ================= shared tiling constants =================================
constexpr int KC      = 32;
constexpr int AST     = 20;                 // padded b32 words per 32-elt row
constexpr int PLANE_W = 128 * AST;          // 2560 words
constexpr int STAGE_W = 4 * PLANE_W;        // Ah, Al, Bh, Bl
constexpr int GEMM_SMEM = 3 * STAGE_W * 4;  // 122880 B (3-stage ring)
constexpr int ATTN_SMEM = 2 * STAGE_W * 4;  // 81920 B

// ================= dense GEMM: pre-split bf16 planes, cp.async =============
// C = A @ Bt^T. A planes [M,K] row-major, Bt planes [N,K] K-major.
// 128x128 CTA tile, 8 warps of 64x32, KC=32, cp.async 3-stage ring.
// EPI: 0 none, 1 +bias, 2 +bias+gelu.  WF: write fp32 C.  WP: write C planes.
template<int EPI, bool WF, bool WP>
__global__ __launch_bounds__(256)
void gemm_mma(const __nv_bfloat16* __restrict__ Ah_, const __nv_bfloat16* __restrict__ Al_,
              const __nv_bfloat16* __restrict__ Bth, const __nv_bfloat16* __restrict__ Btl,
              const float* __restrict__ bias, float* __restrict__ Cf,
              __nv_bfloat16* __restrict__ Ch, __nv_bfloat16* __restrict__ Cl,
              int M, int N, int K)
{
    extern __shared__ uint32_t smw[];
    const uint32_t sbase = smem_u32(smw);
    const int tid  = threadIdx.x;
    const int wid  = tid >> 5, lane = tid & 31;
    const int grp  = lane >> 2, q = lane & 3;
    const int wr   = wid >> 2, wc = wid & 3;
    const int row0 = blockIdx.y * 128;
    const int col0 = blockIdx.x * 128;

    float c[4][4][4];
    #pragma unroll
    for (int mt = 0; mt < 4; mt++)
        #pragma unroll
        for (int nt = 0; nt < 4; nt++)
            #pragma unroll
            for (int e = 0; e < 4; e++) c[mt][nt][e] = 0.f;

    const int T = K / KC;

    auto issue = [&](int i) {
        int k0 = i * KC;
        uint32_t sb = sbase + (uint32_t)((i % 3) * STAGE_W) * 4;
        #pragma unroll
        for (int it = 0; it < 8; it++) {
            int idx = tid + it * 256;
            int plane = idx >> 9, rem = idx & 511;
            int r = rem >> 2, ch = rem & 3;
            const __nv_bfloat16* src;
            if (plane == 0)      src = Ah_ + (size_t)(row0 + r) * K + k0 + ch * 8;
            else if (plane == 1) src = Al_ + (size_t)(row0 + r) * K + k0 + ch * 8;
            else if (plane == 2) src = Bth + (size_t)(col0 + r) * K + k0 + ch * 8;
            else                 src = Btl + (size_t)(col0 + r) * K + k0 + ch * 8;
            cpa16(sb + (uint32_t)(plane * PLANE_W + r * AST + ch * 4) * 4, src);
        }
        cpa_commit();
    };

    issue(0);
    if (T > 1) issue(1);
    for (int i = 0; i < T; i++) {
        if (i + 2 < T) { issue(i + 2); cpa_wait<2>(); }
        else if (i + 1 < T) { cpa_wait<1>(); }
        else { cpa_wait<0>(); }
        __syncthreads();

        const uint32_t* stg = smw + (i % 3) * STAGE_W;
        const uint32_t* Ah = stg;
        const uint32_t* Al = stg + PLANE_W;
        const uint32_t* Bh = stg + 2 * PLANE_W;
        const uint32_t* Bl = stg + 3 * PLANE_W;
        #pragma unroll
        for (int k16 = 0; k16 < 2; k16++) {
            uint32_t bh[4][2], bl[4][2];
            #pragma unroll
            for (int nt = 0; nt < 4; nt++) {
                int brb = (wc * 32 + nt * 8 + grp) * AST + k16 * 8 + q;
                bh[nt][0] = Bh[brb]; bh[nt][1] = Bh[brb + 4];
                bl[nt][0] = Bl[brb]; bl[nt][1] = Bl[brb + 4];
            }
            #pragma unroll
            for (int mt = 0; mt < 4; mt++) {
                int arb = (wr * 64 + mt * 16 + grp) * AST + k16 * 8 + q;
                uint32_t ah[4], al[4];
                ah[0] = Ah[arb];     ah[1] = Ah[arb + 160];
                ah[2] = Ah[arb + 4]; ah[3] = Ah[arb + 164];
                al[0] = Al[arb];     al[1] = Al[arb + 160];
                al[2] = Al[arb + 4]; al[3] = Al[arb + 164];
                #pragma unroll
                for (int nt = 0; nt < 4; nt++) {
                    mma_bf16(c[mt][nt], ah, bh[nt]);
                    mma_bf16(c[mt][nt], ah, bl[nt]);
                    mma_bf16(c[mt][nt], al, bh[nt]);
                }
            }
        }
        __syncthreads();
    }

    #pragma unroll
    for (int mt = 0; mt < 4; mt++) {
        #pragma unroll
        for (int nt = 0; nt < 4; nt++) {
            int col = col0 + wc * 32 + nt * 8 + 2 * q;
            int r0  = row0 + wr * 64 + mt * 16 + grp;
            float2 v0 = make_float2(c[mt][nt][0], c[mt][nt][1]);
            float2 v1 = make_float2(c[mt][nt][2], c[mt][nt][3]);
            if (EPI >= 1) {
                float b0 = bias[col], b1 = bias[col + 1];
                v0.x += b0; v0.y += b1; v1.x += b0; v1.y += b1;
            }
            if (EPI == 2) {
                v0.x = 0.5f * v0.x * (1.0f + erff(v0.x * 0.70710678118654752f));
                v0.y = 0.5f * v0.y * (1.0f + erff(v0.y * 0.70710678118654752f));
                v1.x = 0.5f * v1.x * (1.0f + erff(v1.x * 0.70710678118654752f));
                v1.y = 0.5f * v1.y * (1.0f + erff(v1.y * 0.70710678118654752f));
            }
            if (WF) {
                *(float2*)&Cf[(size_t)r0 * N + col]       = v0;
                *(float2*)&Cf[(size_t)(r0 + 8) * N + col] = v1;
            }
            if (WP) {
                uint32_t hw, lw;
                split2(v0.x, v0.y, hw, lw);
                *(uint32_t*)&Ch[(size_t)r0 * N + col] = hw;
                *(uint32_t*)&Cl[(size_t)r0 * N + col] = lw;
                split2(v1.x, v1.y, hw, lw);
                *(uint32_t*)&Ch[(size_t)(r0 + 8) * N + col] = hw;
                *(uint32_t*)&Cl[(size_t)(r0 + 8) * N + col] = lw;
            }
        }
    }
}

// ================= attention phase A: S = Q K^T /8 + bias, mask, expsum ====
__global__ __launch_bounds__(256)
void attn_score(const __nv_bfloat16* __restrict__ qh, const __nv_bfloat16* __restrict__ ql,
                const float* __restrict__ sw, const unsigned char* __restrict__ mask8,
                const float* __restrict__ sa, const float* __restrict__ tb,
                float* __restrict__ S_out, float* __restrict__ rowsum)
{
    extern __shared__ uint32_t smw[];
    __shared__ float s_rb[128];
    __shared__ float s_sum[128];
    const uint32_t sbase = smem_u32(smw);
    const int tid  = threadIdx.x;
    const int wid  = tid >> 5, lane = tid & 31;
    const int grp  = lane >> 2, q = lane & 3;
    const int wr   = wid >> 2, wc = wid & 3;
    const int bh = blockIdx.z, b = bh >> 3, h = bh & 7;
    const int row0 = blockIdx.y * 128;
    const int col0 = blockIdx.x * 128;

    const size_t qbase = (size_t)b * Sn * QKVN + h * DKn;        // Q cols
    const size_t kbase = (size_t)b * Sn * QKVN + Dn + h * DKn;   // K cols

    // issue both K-chunks (K=64)
    #pragma unroll
    for (int s = 0; s < 2; s++) {
        int k0 = s * KC;
        uint32_t sb = sbase + (uint32_t)(s * STAGE_W) * 4;
        #pragma unroll
        for (int it = 0; it < 8; it++) {
            int idx = tid + it * 256;
            int plane = idx >> 9, rem = idx & 511;
            int r = rem >> 2, ch = rem & 3;
            const __nv_bfloat16* src;
            if (plane == 0)      src = qh + qbase + (size_t)(row0 + r) * QKVN + k0 + ch * 8;
            else if (plane == 1) src = ql + qbase + (size_t)(row0 + r) * QKVN + k0 + ch * 8;
            else if (plane == 2) src = qh + kbase + (size_t)(col0 + r) * QKVN + k0 + ch * 8;
            else                 src = ql + kbase + (size_t)(col0 + r) * QKVN + k0 + ch * 8;
            cpa16(sb + (uint32_t)(plane * PLANE_W + r * AST + ch * 4) * 4, src);
        }
    }
    cpa_commit();

    if (tid < 128) {
        int row = row0 + tid;
        const float* swp = sw + ((size_t)b * Sn + row) * 4;
        const float* sap = sa + h * 4;
        s_rb[tid] = tb[h] + sap[0]*swp[0] + sap[1]*swp[1]
                          + sap[2]*swp[2] + sap[3]*swp[3];
        s_sum[tid] = 0.f;
    }

    float c[4][4][4];
    #pragma unroll
    for (int mt = 0; mt < 4; mt++)
        #pragma unroll
        for (int nt = 0; nt < 4; nt++)
            #pragma unroll
            for (int e = 0; e < 4; e++) c[mt][nt][e] = 0.f;

    cpa_wait<0>();
    __syncthreads();

    #pragma unroll
    for (int s = 0; s < 2; s++) {
        const uint32_t* stg = smw + s * STAGE_W;
        const uint32_t* Ah = stg;
        const uint32_t* Al = stg + PLANE_W;
        const uint32_t* Bh = stg + 2 * PLANE_W;
        const uint32_t* Bl = stg + 3 * PLANE_W;
        #pragma unroll
        for (int k16 = 0; k16 < 2; k16++) {
            uint32_t bh2[4][2], bl2[4][2];
            #pragma unroll
            for (int nt = 0; nt < 4; nt++) {
                int brb = (wc * 32 + nt * 8 + grp) * AST + k16 * 8 + q;
                bh2[nt][0] = Bh[brb]; bh2[nt][1] = Bh[brb + 4];
                bl2[nt][0] = Bl[brb]; bl2[nt][1] = Bl[brb + 4];
            }
            #pragma unroll
            for (int mt = 0; mt < 4; mt++) {
                int arb = (wr * 64 + mt * 16 + grp) * AST + k16 * 8 + q;
                uint32_t ah[4], al[4];
                ah[0] = Ah[arb];     ah[1] = Ah[arb + 160];
                ah[2] = Ah[arb + 4]; ah[3] = Ah[arb + 164];
                al[0] = Al[arb];     al[1] = Al[arb + 160];
                al[2] = Al[arb + 4]; al[3] = Al[arb + 164];
                #pragma unroll
                for (int nt = 0; nt < 4; nt++) {
                    mma_bf16(c[mt][nt], ah, bh2[nt]);
                    mma_bf16(c[mt][nt], ah, bl2[nt]);
                    mma_bf16(c[mt][nt], al, bh2[nt]);
                }
            }
        }
    }

    float* S = S_out + (size_t)bh * Sn * Sn;
    float psum[4][2];
    #pragma unroll
    for (int mt = 0; mt < 4; mt++) { psum[mt][0] = 0.f; psum[mt][1] = 0.f; }

    #pragma unroll
    for (int mt = 0; mt < 4; mt++) {
        #pragma unroll
        for (int nt = 0; nt < 4; nt++) {
            int col = col0 + wc * 32 + nt * 8 + 2 * q;
            int r0  = row0 + wr * 64 + mt * 16 + grp;
            #pragma unroll
            for (int half = 0; half < 2; half++) {
                int r = r0 + half * 8;
                float2 v = make_float2(c[mt][nt][2*half], c[mt][nt][2*half + 1]);
                float rb = s_rb[r - row0];
                v.x = v.x * 0.125f + rb;
                v.y = v.y * 0.125f + rb;
                uchar2 m2 = *(const uchar2*)&mask8[(size_t)r * Sn + col];
                if (m2.x == 0) v.x = -1e9f;
                if (m2.y == 0) v.y = -1e9f;
                psum[mt][half] += __expf(v.x) + __expf(v.y);
                *(float2*)&S[(size_t)r * Sn + col] = v;
            }
        }
    }
    // reduce expsum across q lanes, accumulate per-row into smem then gmem
    #pragma unroll
    for (int mt = 0; mt < 4; mt++) {
        #pragma unroll
        for (int half = 0; half < 2; half++) {
            float t = psum[mt][half];
            t += __shfl_xor_sync(0xffffffffu, t, 1);
            t += __shfl_xor_sync(0xffffffffu, t, 2);
            if (q == 0)
                atomicAdd(&s_sum[wr * 64 + mt * 16 + half * 8 + grp], t);
        }
    }
    __syncthreads();
    if (tid < 128)
        atomicAdd(&rowsum[(size_t)bh * Sn + row0 + tid], s_sum[tid]);
}

// ================= attention phase C: p=exp(S)/sum, write P, ctx = P @ V ===
constexpr int PV_APL   = 128 * AST;
constexpr int PV_BPL   = 64 * AST;
constexpr int PV_STAGE = 2 * PV_APL + 2 * PV_BPL;
constexpr int PV_SMEM  = 2 * PV_STAGE * 4;

__global__ __launch_bounds__(256)
void attn_pv(float* __restrict__ Pm, const float* __restrict__ rowsum,
             const __nv_bfloat16* __restrict__ vth, const __nv_bfloat16* __restrict__ vtl,
             __nv_bfloat16* __restrict__ ctxh, __nv_bfloat16* __restrict__ ctxl)
{
    extern __shared__ uint32_t smw[];
    __shared__ float s_inv[128];
    const int tid  = threadIdx.x;
    const int wid  = tid >> 5, lane = tid & 31;
    const int grp  = lane >> 2, q = lane & 3;
    const int bh = blockIdx.y, b = bh >> 3, h = bh & 7;
    const int m0 = blockIdx.x * 128;

    float* A = Pm + (size_t)bh * Sn * Sn;
    const __nv_bfloat16* Bh_ = vth + (size_t)bh * DKn * Sn;
    const __nv_bfloat16* Bl_ = vtl + (size_t)bh * DKn * Sn;

    if (tid < 128) s_inv[tid] = 1.f / rowsum[(size_t)bh * Sn + m0 + tid];
    __syncthreads();

    float c[8][4];
    #pragma unroll
    for (int nt = 0; nt < 8; nt++)
        #pragma unroll
        for (int e = 0; e < 4; e++) c[nt][e] = 0.f;

    const int T = Sn / KC;   // 64
    float4 ra[4]; uint4 rbh, rbl;

    auto stage_A = [&](uint32_t* stg, int k0) {
        #pragma unroll
        for (int it = 0; it < 4; it++) {
            int idx = tid + it * 256;
            int r = idx >> 3, f = idx & 7;
            float4 v = ra[it];
            float inv = s_inv[r];
            v.x = __expf(v.x) * inv; v.y = __expf(v.y) * inv;
            v.z = __expf(v.z) * inv; v.w = __expf(v.w) * inv;
            *(float4*)&A[(size_t)(m0 + r) * Sn + k0 + f * 4] = v;   // final attn
            int w = r * AST + f * 2;
            uint32_t h0, h1, l0, l1;
            split2(v.x, v.y, h0, l0);
            split2(v.z, v.w, h1, l1);
            stg[w] = h0; stg[w + 1] = h1;
            stg[PV_APL + w] = l0; stg[PV_APL + w + 1] = l1;
        }
        int r = tid >> 2, f = tid & 3;
        int w = r * AST + f * 4;
        *(uint4*)&stg[2 * PV_APL + w] = rbh;
        *(uint4*)&stg[2 * PV_APL + PV_BPL + w] = rbl;
    };
    auto ldg_AB = [&](int k0) {
        #pragma unroll
        for (int it = 0; it < 4; it++) {
            int idx = tid + it * 256;
            int r = idx >> 3, f = idx & 7;
            ra[it] = *(const float4*)&A[(size_t)(m0 + r) * Sn + k0 + f * 4];
        }
        int r = tid >> 2, f = tid & 3;
        rbh = *(const uint4*)&Bh_[(size_t)r * Sn + k0 + f * 8];
        rbl = *(const uint4*)&Bl_[(size_t)r * Sn + k0 + f * 8];
    };

    ldg_AB(0);
    stage_A(smw, 0);
    __syncthreads();

    for (int i = 0; i < T; i++) {
        const uint32_t* stg = smw + (i & 1) * PV_STAGE;
        const uint32_t* Ah = stg;
        const uint32_t* Al = stg + PV_APL;
        const uint32_t* Bhp = stg + 2 * PV_APL;
        const uint32_t* Blp = stg + 2 * PV_APL + PV_BPL;

        if (i + 1 < T) ldg_AB((i + 1) * KC);

        #pragma unroll
        for (int k16 = 0; k16 < 2; k16++) {
            int arb = (wid * 16 + grp) * AST + k16 * 8 + q;
            uint32_t ah[4], al[4];
            ah[0] = Ah[arb];     ah[1] = Ah[arb + 160];
            ah[2] = Ah[arb + 4]; ah[3] = Ah[arb + 164];
            al[0] = Al[arb];     al[1] = Al[arb + 160];
            al[2] = Al[arb + 4]; al[3] = Al[arb + 164];
            #pragma unroll
            for (int nt = 0; nt < 8; nt++) {
                int brb = (nt * 8 + grp) * AST + k16 * 8 + q;
                uint32_t bh2[2], bl2[2];
                bh2[0] = Bhp[brb]; bh2[1] = Bhp[brb + 4];
                bl2[0] = Blp[brb]; bl2[1] = Blp[brb + 4];
                mma_bf16(c[nt], ah, bh2);
                mma_bf16(c[nt], ah, bl2);
                mma_bf16(c[nt], al, bh2);
            }
        }
        __syncthreads();
        if (i + 1 < T) {
            stage_A(smw + ((i + 1) & 1) * PV_STAGE, (i + 1) * KC);
            __syncthreads();
        }
    }

    #pragma unroll
    for (int nt = 0; nt < 8; nt++) {
        int col = h * DKn + nt * 8 + 2 * q;
        int r0  = m0 + wid * 16 + grp;
        uint32_t hw, lw;
        split2(c[nt][0], c[nt][1], hw, lw);
        *(uint32_t*)&ctxh[(size_t)(b * Sn + r0) * Dn + col] = hw;
        *(uint32_t*)&ctxl[(size_t)(b * Sn + r0) * Dn + col] = lw;
        split2(c[nt][2], c[nt][3], hw, lw);
        *(uint32_t*)&ctxh[(size_t)(b * Sn + r0 + 8) * Dn + col] = hw;
        *(uint32_t*)&ctxl[(size_t)(b * Sn + r0 + 8) * Dn + col] = lw;
    }
}

// ============================ small utility kernels ========================
__global__ __launch_bounds__(256)
void zero_f32(float* __restrict__ p, int n)
{
    int i = blockIdx.x * 256 + threadIdx.x;
    if (i < n) p[i] = 0.f;
}

// int32 mask -> uint8 mask (0/1)
__global__ __launch_bounds__(256)
void mask_to_u8(const int* __restrict__ m, unsigned char* __restrict__ m8, int n4)
{
    int i = blockIdx.x * 256 + threadIdx.x;
    if (i >= n4) return;
    int4 v = ((const int4*)m)[i];
    uchar4 o;
    o.x = v.x != 0; o.y = v.y != 0; o.z = v.z != 0; o.w = v.w != 0;
    ((uchar4*)m8)[i] = o;
}

// fp32 -> bf16 hi/lo planes (contiguous)
__global__ __launch_bounds__(256)
void split_planes(const float* __restrict__ src, __nv_bfloat16* __restrict__ h,
                  __nv_bfloat16* __restrict__ l, int n4)
{
    int i = blockIdx.x * 256 + threadIdx.x;
    if (i >= n4) return;
    float4 v = ((const float4*)src)[i];
    uint32_t h0, l0, h1, l1;
    split2(v.x, v.y, h0, l0);
    split2(v.z, v.w, h1, l1);
    ((uint2*)h)[i] = make_uint2(h0, h1);
    ((uint2*)l)[i] = make_uint2(l0, l1);
}

// W[K,N] -> Wt[N,K] bf16 hi/lo planes
__global__ __launch_bounds__(256)
void transpose_w(const float* __restrict__ W, __nv_bfloat16* __restrict__ Wth,
                 __nv_bfloat16* __restrict__ Wtl, int K, int N)
{
    __shared__ float t[32][33];
    int x = blockIdx.x * 32 + threadIdx.x;
    #pragma unroll
    for (int j = 0; j < 4; j++)
        t[threadIdx.y + j * 8][threadIdx.x] =
            W[(size_t)(blockIdx.y * 32 + threadIdx.y + j * 8) * N + x];
    __syncthreads();
    int x2 = blockIdx.y * 32 + threadIdx.x;
    #pragma unroll
    for (int j = 0; j < 4; j++) {
        float v = t[threadIdx.x][threadIdx.y + j * 8];
        __nv_bfloat16 hi = __float2bfloat16_rn(v);
        size_t o = (size_t)(blockIdx.x * 32 + threadIdx.y + j * 8) * K + x2;
        Wth[o] = hi;
        Wtl[o] = __float2bfloat16_rn(v - __bfloat162float(hi));
    }
}

// V slice of qkv planes -> vt[bh][64][Sn] bf16 hi/lo
__global__ __launch_bounds__(256)
void transpose_v(const __nv_bfloat16* __restrict__ qh, const __nv_bfloat16* __restrict__ ql,
                 __nv_bfloat16* __restrict__ vth, __nv_bfloat16* __restrict__ vtl)
{
    __shared__ float t[32][33];
    const int bh = blockIdx.z, b = bh >> 3, h = bh & 7;
    const int s0 = blockIdx.x * 32;
    const int d0 = blockIdx.y * 32;
    const int vcol = 2 * Dn + h * DKn;
    #pragma unroll
    for (int j = 0; j < 4; j++) {
        size_t o = (size_t)(b * Sn + s0 + threadIdx.y + j * 8) * QKVN + vcol + d0 + threadIdx.x;
        t[threadIdx.y + j * 8][threadIdx.x] =
            __bfloat162float(qh[o]) + __bfloat162float(ql[o]);
    }
    __syncthreads();
    #pragma unroll
    for (int j = 0; j < 4; j++) {
        float v = t[threadIdx.x][threadIdx.y + j * 8];
        __nv_bfloat16 hi = __float2bfloat16_rn(v);
        size_t o = ((size_t)bh * DKn + d0 + threadIdx.y + j * 8) * Sn + s0 + threadIdx.x;
        vth[o] = hi;
        vtl[o] = __float2bfloat16_rn(v - __bfloat162float(hi));
    }
}

// ---------------------------------------------------------------------------
// out = LayerNorm(a + r) * g + b   (+ optional bf16 hi/lo planes of out)
// ---------------------------------------------------------------------------
__global__ __launch_bounds__(256)
void add_ln(const float* __restrict__ a, const float* __restrict__ r,
            const float* __restrict__ g, const float* __restrict__ be,
            float* __restrict__ out, __nv_bfloat16* __restrict__ oh,
            __nv_bfloat16* __restrict__ ol)
{
    const int row = blockIdx.x, tid = threadIdx.x;
    const float* ap = a + (size_t)row * Dn;
    const float* rp = r + (size_t)row * Dn;
    float v0 = ap[tid]       + rp[tid];
    float v1 = ap[tid + 256] + rp[tid + 256];

    __shared__ float red[8];
    __shared__ float s_mu, s_inv;
    const int w = tid >> 5, lane = tid & 31;

    float s = v0 + v1;
    #pragma unroll
    for (int o = 16; o > 0; o >>= 1) s += __shfl_xor_sync(0xffffffffu, s, o);
    if (lane == 0) red[w] = s;
    __syncthreads();
    if (tid < 32) {
        float t = (tid < 8) ? red[tid] : 0.f;
        #pragma unroll
        for (int o = 4; o > 0; o >>= 1) t += __shfl_xor_sync(0xffffffffu, t, o);
        if (tid == 0) s_mu = t * (1.f / Dn);
    }
    __syncthreads();
    float mu = s_mu;
    float d0 = v0 - mu, d1 = v1 - mu;

    float qv = d0*d0 + d1*d1;
    #pragma unroll
    for (int o = 16; o > 0; o >>= 1) qv += __shfl_xor_sync(0xffffffffu, qv, o);
    __syncthreads();
    if (lane == 0) red[w] = qv;
    __syncthreads();
    if (tid < 32) {
        float t = (tid < 8) ? red[tid] : 0.f;
        #pragma unroll
        for (int o = 4; o > 0; o >>= 1) t += __shfl_xor_sync(0xffffffffu, t, o);
        if (tid == 0) s_inv = rsqrtf(t * (1.f / Dn) + 1e-6f);
    }
    __syncthreads();
    float inv = s_inv;
    float o0 = d0 * inv * g[tid]       + be[tid];
    float o1 = d1 * inv * g[tid + 256] + be[tid + 256];
    float* op = out + (size_t)row * Dn;
    op[tid]       = o0;
    op[tid + 256] = o1;
    if (oh) {
        __nv_bfloat16 h0 = __float2bfloat16_rn(o0);
        __nv_bfloat16 h1 = __float2bfloat16_rn(o1);
        size_t base = (size_t)row * Dn;
        oh[base + tid]       = h0;
        oh[base + tid + 256] = h1;
        ol[base + tid]       = __float2bfloat16_rn(o0 - __bfloat162float(h0));
        ol[base + tid + 256] = __float2bfloat16_rn(o1 - __bfloat162float(h1));
    }
}

// ---------------------------------------------------------------------------
extern "C" void kernel_launch(void* const* d_in, const int* in_sizes, int n_in,
                              void* d_out, int out_size)
{
    const float* x    = (const float*)d_in[0];
    const float* sw   = (const float*)d_in[1];
    const int*   mask = (const int*)  d_in[2];
    const float* Wq   = (const float*)d_in[3];
    const float* Wk   = (const float*)d_in[4];
    const float* Wv   = (const float*)d_in[5];
    const float* Wo   = (const float*)d_in[6];
    const float* bo   = (const float*)d_in[7];
    const float* sa   = (const float*)d_in[8];
    const float* tb   = (const float*)d_in[9];
    const float* ln1g = (const float*)d_in[10];
    const float* ln1b = (const float*)d_in[11];
    const float* ln2g = (const float*)d_in[12];
    const float* ln2b = (const float*)d_in[13];
    const float* W1   = (const float*)d_in[14];
    const float* b1   = (const float*)d_in[15];
    const float* W2   = (const float*)d_in[16];
    const float* b2   = (const float*)d_in[17];

    float* out_x2   = (float*)d_out;
    float* out_attn = (float*)d_out + (size_t)BSn * Dn;

    float *x1, *t2, *rowsum;
    unsigned char* mask8;
    __nv_bfloat16 *xh, *xl, *qkvh, *qkvl, *ctxh, *ctxl, *x1h, *x1l, *ffh, *ffl;
    __nv_bfloat16 *wqkv_h, *wqkv_l, *wo_h, *wo_l, *w1_h, *w1_l, *w2_h, *w2_l, *vth, *vtl;
    cudaGetSymbolAddress((void**)&x1,     g_x1);
    cudaGetSymbolAddress((void**)&t2,     g_t2);
    cudaGetSymbolAddress((void**)&rowsum, g_rowsum);
    cudaGetSymbolAddress((void**)&mask8,  g_mask8);
    cudaGetSymbolAddress((void**)&xh,     g_x_h);
    cudaGetSymbolAddress((void**)&xl,     g_x_l);
    cudaGetSymbolAddress((void**)&qkvh,   g_qkv_h);
    cudaGetSymbolAddress((void**)&qkvl,   g_qkv_l);
    cudaGetSymbolAddress((void**)&ctxh,   g_ctx_h);
    cudaGetSymbolAddress((void**)&ctxl,   g_ctx_l);
    cudaGetSymbolAddress((void**)&x1h,    g_x1_h);
    cudaGetSymbolAddress((void**)&x1l,    g_x1_l);
    cudaGetSymbolAddress((void**)&ffh,    g_ff_h);
    cudaGetSymbolAddress((void**)&ffl,    g_ff_l);
    cudaGetSymbolAddress((void**)&wqkv_h, g_wqkv_h);
    cudaGetSymbolAddress((void**)&wqkv_l, g_wqkv_l);
    cudaGetSymbolAddress((void**)&wo_h,   g_wo_h);
    cudaGetSymbolAddress((void**)&wo_l,   g_wo_l);
    cudaGetSymbolAddress((void**)&w1_h,   g_w1_h);
    cudaGetSymbolAddress((void**)&w1_l,   g_w1_l);
    cudaGetSymbolAddress((void**)&w2_h,   g_w2_h);
    cudaGetSymbolAddress((void**)&w2_l,   g_w2_l);
    cudaGetSymbolAddress((void**)&vth,    g_vt_h);
    cudaGetSymbolAddress((void**)&vtl,    g_vt_l);

    cudaFuncSetAttribute(gemm_mma<0,false,true>, cudaFuncAttributeMaxDynamicSharedMemorySize, GEMM_SMEM);
    cudaFuncSetAttribute(gemm_mma<1,true,false>, cudaFuncAttributeMaxDynamicSharedMemorySize, GEMM_SMEM);
    cudaFuncSetAttribute(gemm_mma<2,false,true>, cudaFuncAttributeMaxDynamicSharedMemorySize, GEMM_SMEM);
    cudaFuncSetAttribute(attn_score, cudaFuncAttributeMaxDynamicSharedMemorySize, ATTN_SMEM);
    cudaFuncSetAttribute(attn_pv,    cudaFuncAttributeMaxDynamicSharedMemorySize, PV_SMEM);

    dim3 tb8(32, 8);
    dim3 blk(256);

    // weight transposes + input split + mask compress
    transpose_w<<<dim3(Dn/32,  Dn/32),  tb8>>>(Wq, wqkv_h,            wqkv_l,            Dn, Dn);
    transpose_w<<<dim3(Dn/32,  Dn/32),  tb8>>>(Wk, wqkv_h + Dn*Dn,    wqkv_l + Dn*Dn,    Dn, Dn);
    transpose_w<<<dim3(Dn/32,  Dn/32),  tb8>>>(Wv, wqkv_h + 2*Dn*Dn,  wqkv_l + 2*Dn*Dn,  Dn, Dn);
    transpose_w<<<dim3(Dn/32,  Dn/32),  tb8>>>(Wo, wo_h, wo_l, Dn, Dn);
    transpose_w<<<dim3(DFFn/32, Dn/32), tb8>>>(W1, w1_h, w1_l, Dn, DFFn);
    transpose_w<<<dim3(Dn/32, DFFn/32), tb8>>>(W2, w2_h, w2_l, DFFn, Dn);
    split_planes<<<(BSn*Dn/4 + 255)/256, blk>>>(x, xh, xl, BSn*Dn/4);
    zero_f32<<<(BHn*Sn + 255)/256, blk>>>(rowsum, BHn*Sn);
    mask_to_u8<<<(Sn*Sn/4 + 255)/256, blk>>>(mask, mask8, Sn*Sn/4);

    // fused QKV projection -> planes
    gemm_mma<0,false,true><<<dim3(QKVN/128, BSn/128), blk, GEMM_SMEM>>>(
        xh, xl, wqkv_h, wqkv_l, nullptr, nullptr, qkvh, qkvl, BSn, QKVN, Dn);

    // V transpose for PV phase
    transpose_v<<<dim3(Sn/32, DKn/32, BHn), tb8>>>(qkvh, qkvl, vth, vtl);

    // attention: raw scores + expsums -> normalize-in-pv (writes final attn)
    attn_score<<<dim3(Sn/128, Sn/128, BHn), blk, ATTN_SMEM>>>(
        qkvh, qkvl, sw, mask8, sa, tb, out_attn, rowsum);
    attn_pv<<<dim3(Sn/128, BHn), blk, PV_SMEM>>>(
        out_attn, rowsum, vth, vtl, ctxh, ctxl);

    // output projection + bias
    gemm_mma<1,true,false><<<dim3(Dn/128, BSn/128), blk, GEMM_SMEM>>>(
        ctxh, ctxl, wo_h, wo_l, bo, t2, nullptr, nullptr, BSn, Dn, Dn);
    add_ln<<<BSn, blk>>>(x, t2, ln1g, ln1b, x1, x1h, x1l);

    // FFN
    gemm_mma<2,false,true><<<dim3(DFFn/128, BSn/128), blk, GEMM_SMEM>>>(
        x1h, x1l, w1_h, w1_l, b1, nullptr, ffh, ffl, BSn, DFFn, Dn);
    gemm_mma<1,true,false><<<dim3(Dn/128, BSn/128), blk, GEMM_SMEM>>>(
        ffh, ffl, w2_h, w2_l, b2, t2, nullptr, nullptr, BSn, Dn, DFFn);

    add_ln<<<BSn, blk>>>(x1, t2, ln2g, ln2b, out_x2, nullptr, nullptr);
}

// round 15
// speedup vs baseline: 1.3971x; 1.0225x over previous
#include <cuda_runtime.h>
#include <cuda_bf16.h>
#include <math.h>
#include <stdint.h>
#include <stddef.h>

// Problem dims (fixed by reference)
constexpr int Bn  = 2;
constexpr int Sn  = 2048;
constexpr int Dn  = 512;
constexpr int Hn  = 8;
constexpr int DKn = 64;
constexpr int DFFn= 2048;
constexpr int BSn = Bn * Sn;          // 4096 token rows
constexpr int QKVN = 3 * Dn;          // 1536 fused qkv width
constexpr int BHn = Bn * Hn;          // 16 batched heads

// ---------------- scratch (device globals; no allocation allowed) ----------
__device__ float g_x1  [BSn * Dn];
__device__ float g_t2  [BSn * Dn];
__device__ float g_rowsum[BHn * Sn];
__device__ unsigned char g_mask8[(size_t)Sn * Sn];
// activation bf16 hi/lo planes
__device__ __nv_bfloat16 g_x_h  [BSn * Dn],   g_x_l  [BSn * Dn];
__device__ __nv_bfloat16 g_qkv_h[BSn * QKVN], g_qkv_l[BSn * QKVN];
__device__ __nv_bfloat16 g_ctx_h[BSn * Dn],   g_ctx_l[BSn * Dn];
__device__ __nv_bfloat16 g_x1_h [BSn * Dn],   g_x1_l [BSn * Dn];
__device__ __nv_bfloat16 g_ff_h [BSn * DFFn], g_ff_l [BSn * DFFn];
// weight bf16 hi/lo planes (K-major, [N,K])
__device__ __nv_bfloat16 g_wqkv_h[QKVN * Dn], g_wqkv_l[QKVN * Dn];
__device__ __nv_bfloat16 g_wo_h  [Dn * Dn],   g_wo_l  [Dn * Dn];
__device__ __nv_bfloat16 g_w1_h  [DFFn * Dn], g_w1_l  [DFFn * Dn];
__device__ __nv_bfloat16 g_w2_h  [Dn * DFFn], g_w2_l  [Dn * DFFn];
// V transposed per (b,h): [bh][64][Sn] bf16 hi/lo
__device__ __nv_bfloat16 g_vt_h[BHn * DKn * Sn], g_vt_l[BHn * DKn * Sn];

// ============================ PTX helpers ==================================
__device__ __forceinline__ uint32_t smem_u32(const void* p) {
    uint32_t a;
    asm("{ .reg .u64 t; cvta.to.shared.u64 t, %1; cvt.u32.u64 %0, t; }"
        : "=r"(a) : "l"(p));
    return a;
}
__device__ __forceinline__ void mma_bf16(float* c, const uint32_t* a, const uint32_t* b) {
    asm volatile("mma.sync.aligned.m16n8k16.row.col.f32.bf16.bf16.f32 "
        "{%0,%1,%2,%3}, {%4,%5,%6,%7}, {%8,%9}, {%0,%1,%2,%3};"
        : "+f"(c[0]), "+f"(c[1]), "+f"(c[2]), "+f"(c[3])
        : "r"(a[0]), "r"(a[1]), "r"(a[2]), "r"(a[3]), "r"(b[0]), "r"(b[1]));
}
__device__ __forceinline__ uint32_t pk(__nv_bfloat16 a, __nv_bfloat16 b) {
    return (uint32_t)__bfloat16_as_ushort(a) | ((uint32_t)__bfloat16_as_ushort(b) << 16);
}
__device__ __forceinline__ void split2(float x, float y, uint32_t& hw, uint32_t& lw) {
    __nv_bfloat16 h0 = __float2bfloat16_rn(x);
    __nv_bfloat16 h1 = __float2bfloat16_rn(y);
    hw = pk(h0, h1);
    lw = pk(__float2bfloat16_rn(x - __bfloat162float(h0)),
            __float2bfloat16_rn(y - __bfloat162float(h1)));
}
__device__ __forceinline__ void cpa16(uint32_t dst, const void* src) {
    asm volatile("cp.async.cg.shared.global [%0], [%1], 16;" :: "r"(dst), "l"(src));
}
__device__ __forceinline__ void cpa_commit() {
    asm volatile("cp.async.commit_group;" ::: "memory");
}
template<int N> __device__ __forceinline__ void cpa_wait() {
    asm volatile("cp.async.wait_group %0;" :: "n"(N) : "memory");
}

// ================= shared tiling constants =================================
constexpr int KC      = 32;
constexpr int AST     = 20;                 // padded b32 words per 32-elt row
constexpr int PLANE_W = 128 * AST;          // 2560 words
constexpr int STAGE_W = 4 * PLANE_W;        // Ah, Al, Bh, Bl
constexpr int GEMM_SMEM = 2 * STAGE_W * 4;  // 81920 B (double buffer, 2 CTAs/SM)

// ================= dense GEMM: pre-split bf16 planes, cp.async =============
// C = A @ Bt^T. A planes [M,K] row-major, Bt planes [N,K] K-major.
// 128x128 CTA tile, 8 warps of 64x32, KC=32, cp.async double buffer.
// EPI: 0 none, 1 +bias, 2 +bias+gelu.  WF: write fp32 C.  WP: write C planes.
template<int EPI, bool WF, bool WP>
__global__ __launch_bounds__(256)
void gemm_mma(const __nv_bfloat16* __restrict__ Ah_, const __nv_bfloat16* __restrict__ Al_,
              const __nv_bfloat16* __restrict__ Bth, const __nv_bfloat16* __restrict__ Btl,
              const float* __restrict__ bias, float* __restrict__ Cf,
              __nv_bfloat16* __restrict__ Ch, __nv_bfloat16* __restrict__ Cl,
              int M, int N, int K)
{
    extern __shared__ uint32_t smw[];
    const uint32_t sbase = smem_u32(smw);
    const int tid  = threadIdx.x;
    const int wid  = tid >> 5, lane = tid & 31;
    const int grp  = lane >> 2, q = lane & 3;
    const int wr   = wid >> 2, wc = wid & 3;
    const int row0 = blockIdx.y * 128;
    const int col0 = blockIdx.x * 128;

    float c[4][4][4];
    #pragma unroll
    for (int mt = 0; mt < 4; mt++)
        #pragma unroll
        for (int nt = 0; nt < 4; nt++)
            #pragma unroll
            for (int e = 0; e < 4; e++) c[mt][nt][e] = 0.f;

    const int T = K / KC;

    auto issue = [&](int i) {
        int k0 = i * KC;
        uint32_t sb = sbase + (uint32_t)((i & 1) * STAGE_W) * 4;
        #pragma unroll
        for (int it = 0; it < 8; it++) {
            int idx = tid + it * 256;
            int plane = idx >> 9, rem = idx & 511;
            int r = rem >> 2, ch = rem & 3;
            const __nv_bfloat16* src;
            if (plane == 0)      src = Ah_ + (size_t)(row0 + r) * K + k0 + ch * 8;
            else if (plane == 1) src = Al_ + (size_t)(row0 + r) * K + k0 + ch * 8;
            else if (plane == 2) src = Bth + (size_t)(col0 + r) * K + k0 + ch * 8;
            else                 src = Btl + (size_t)(col0 + r) * K + k0 + ch * 8;
            cpa16(sb + (uint32_t)(plane * PLANE_W + r * AST + ch * 4) * 4, src);
        }
        cpa_commit();
    };

    issue(0);
    for (int i = 0; i < T; i++) {
        if (i + 1 < T) { issue(i + 1); cpa_wait<1>(); }
        else           { cpa_wait<0>(); }
        __syncthreads();

        const uint32_t* stg = smw + (i & 1) * STAGE_W;
        const uint32_t* Ah = stg;
        const uint32_t* Al = stg + PLANE_W;
        const uint32_t* Bh = stg + 2 * PLANE_W;
        const uint32_t* Bl = stg + 3 * PLANE_W;
        #pragma unroll
        for (int k16 = 0; k16 < 2; k16++) {
            uint32_t bh[4][2], bl[4][2];
            #pragma unroll
            for (int nt = 0; nt < 4; nt++) {
                int brb = (wc * 32 + nt * 8 + grp) * AST + k16 * 8 + q;
                bh[nt][0] = Bh[brb]; bh[nt][1] = Bh[brb + 4];
                bl[nt][0] = Bl[brb]; bl[nt][1] = Bl[brb + 4];
            }
            #pragma unroll
            for (int mt = 0; mt < 4; mt++) {
                int arb = (wr * 64 + mt * 16 + grp) * AST + k16 * 8 + q;
                uint32_t ah[4], al[4];
                ah[0] = Ah[arb];     ah[1] = Ah[arb + 160];
                ah[2] = Ah[arb + 4]; ah[3] = Ah[arb + 164];
                al[0] = Al[arb];     al[1] = Al[arb + 160];
                al[2] = Al[arb + 4]; al[3] = Al[arb + 164];
                #pragma unroll
                for (int nt = 0; nt < 4; nt++) {
                    mma_bf16(c[mt][nt], ah, bh[nt]);
                    mma_bf16(c[mt][nt], ah, bl[nt]);
                    mma_bf16(c[mt][nt], al, bh[nt]);
                }
            }
        }
        __syncthreads();
    }

    #pragma unroll
    for (int mt = 0; mt < 4; mt++) {
        #pragma unroll
        for (int nt = 0; nt < 4; nt++) {
            int col = col0 + wc * 32 + nt * 8 + 2 * q;
            int r0  = row0 + wr * 64 + mt * 16 + grp;
            float2 v0 = make_float2(c[mt][nt][0], c[mt][nt][1]);
            float2 v1 = make_float2(c[mt][nt][2], c[mt][nt][3]);
            if (EPI >= 1) {
                float b0 = bias[col], b1 = bias[col + 1];
                v0.x += b0; v0.y += b1; v1.x += b0; v1.y += b1;
            }
            if (EPI == 2) {
                v0.x = 0.5f * v0.x * (1.0f + erff(v0.x * 0.70710678118654752f));
                v0.y = 0.5f * v0.y * (1.0f + erff(v0.y * 0.70710678118654752f));
                v1.x = 0.5f * v1.x * (1.0f + erff(v1.x * 0.70710678118654752f));
                v1.y = 0.5f * v1.y * (1.0f + erff(v1.y * 0.70710678118654752f));
            }
            if (WF) {
                *(float2*)&Cf[(size_t)r0 * N + col]       = v0;
                *(float2*)&Cf[(size_t)(r0 + 8) * N + col] = v1;
            }
            if (WP) {
                uint32_t hw, lw;
                split2(v0.x, v0.y, hw, lw);
                *(uint32_t*)&Ch[(size_t)r0 * N + col] = hw;
                *(uint32_t*)&Cl[(size_t)r0 * N + col] = lw;
                split2(v1.x, v1.y, hw, lw);
                *(uint32_t*)&Ch[(size_t)(r0 + 8) * N + col] = hw;
                *(uint32_t*)&Cl[(size_t)(r0 + 8) * N + col] = lw;
            }
        }
    }
}

// ================= attention phase A: S = Q K^T /8 + bias, mask, expsum ====
__global__ __launch_bounds__(256)
void attn_score(const __nv_bfloat16* __restrict__ qh, const __nv_bfloat16* __restrict__ ql,
                const float* __restrict__ sw, const unsigned char* __restrict__ mask8,
                const float* __restrict__ sa, const float* __restrict__ tb,
                float* __restrict__ S_out, float* __restrict__ rowsum)
{
    extern __shared__ uint32_t smw[];
    __shared__ float s_rb[128];
    __shared__ float s_sum[128];
    const uint32_t sbase = smem_u32(smw);
    const int tid  = threadIdx.x;
    const int wid  = tid >> 5, lane = tid & 31;
    const int grp  = lane >> 2, q = lane & 3;
    const int wr   = wid >> 2, wc = wid & 3;
    const int bh = blockIdx.z, b = bh >> 3, h = bh & 7;
    const int row0 = blockIdx.y * 128;
    const int col0 = blockIdx.x * 128;

    const size_t qbase = (size_t)b * Sn * QKVN + h * DKn;        // Q cols
    const size_t kbase = (size_t)b * Sn * QKVN + Dn + h * DKn;   // K cols

    // issue both K-chunks (K=64)
    #pragma unroll
    for (int s = 0; s < 2; s++) {
        int k0 = s * KC;
        uint32_t sb = sbase + (uint32_t)(s * STAGE_W) * 4;
        #pragma unroll
        for (int it = 0; it < 8; it++) {
            int idx = tid + it * 256;
            int plane = idx >> 9, rem = idx & 511;
            int r = rem >> 2, ch = rem & 3;
            const __nv_bfloat16* src;
            if (plane == 0)      src = qh + qbase + (size_t)(row0 + r) * QKVN + k0 + ch * 8;
            else if (plane == 1) src = ql + qbase + (size_t)(row0 + r) * QKVN + k0 + ch * 8;
            else if (plane == 2) src = qh + kbase + (size_t)(col0 + r) * QKVN + k0 + ch * 8;
            else                 src = ql + kbase + (size_t)(col0 + r) * QKVN + k0 + ch * 8;
            cpa16(sb + (uint32_t)(plane * PLANE_W + r * AST + ch * 4) * 4, src);
        }
    }
    cpa_commit();

    if (tid < 128) {
        int row = row0 + tid;
        const float* swp = sw + ((size_t)b * Sn + row) * 4;
        const float* sap = sa + h * 4;
        s_rb[tid] = tb[h] + sap[0]*swp[0] + sap[1]*swp[1]
                          + sap[2]*swp[2] + sap[3]*swp[3];
        s_sum[tid] = 0.f;
    }

    float c[4][4][4];
    #pragma unroll
    for (int mt = 0; mt < 4; mt++)
        #pragma unroll
        for (int nt = 0; nt < 4; nt++)
            #pragma unroll
            for (int e = 0; e < 4; e++) c[mt][nt][e] = 0.f;

    cpa_wait<0>();
    __syncthreads();

    #pragma unroll
    for (int s = 0; s < 2; s++) {
        const uint32_t* stg = smw + s * STAGE_W;
        const uint32_t* Ah = stg;
        const uint32_t* Al = stg + PLANE_W;
        const uint32_t* Bh = stg + 2 * PLANE_W;
        const uint32_t* Bl = stg + 3 * PLANE_W;
        #pragma unroll
        for (int k16 = 0; k16 < 2; k16++) {
            uint32_t bh2[4][2], bl2[4][2];
            #pragma unroll
            for (int nt = 0; nt < 4; nt++) {
                int brb = (wc * 32 + nt * 8 + grp) * AST + k16 * 8 + q;
                bh2[nt][0] = Bh[brb]; bh2[nt][1] = Bh[brb + 4];
                bl2[nt][0] = Bl[brb]; bl2[nt][1] = Bl[brb + 4];
            }
            #pragma unroll
            for (int mt = 0; mt < 4; mt++) {
                int arb = (wr * 64 + mt * 16 + grp) * AST + k16 * 8 + q;
                uint32_t ah[4], al[4];
                ah[0] = Ah[arb];     ah[1] = Ah[arb + 160];
                ah[2] = Ah[arb + 4]; ah[3] = Ah[arb + 164];
                al[0] = Al[arb];     al[1] = Al[arb + 160];
                al[2] = Al[arb + 4]; al[3] = Al[arb + 164];
                #pragma unroll
                for (int nt = 0; nt < 4; nt++) {
                    mma_bf16(c[mt][nt], ah, bh2[nt]);
                    mma_bf16(c[mt][nt], ah, bl2[nt]);
                    mma_bf16(c[mt][nt], al, bh2[nt]);
                }
            }
        }
    }

    float* S = S_out + (size_t)bh * Sn * Sn;
    float psum[4][2];
    #pragma unroll
    for (int mt = 0; mt < 4; mt++) { psum[mt][0] = 0.f; psum[mt][1] = 0.f; }

    #pragma unroll
    for (int mt = 0; mt < 4; mt++) {
        #pragma unroll
        for (int nt = 0; nt < 4; nt++) {
            int col = col0 + wc * 32 + nt * 8 + 2 * q;
            int r0  = row0 + wr * 64 + mt * 16 + grp;
            #pragma unroll
            for (int half = 0; half < 2; half++) {
                int r = r0 + half * 8;
                float2 v = make_float2(c[mt][nt][2*half], c[mt][nt][2*half + 1]);
                float rb = s_rb[r - row0];
                v.x = v.x * 0.125f + rb;
                v.y = v.y * 0.125f + rb;
                uchar2 m2 = *(const uchar2*)&mask8[(size_t)r * Sn + col];
                if (m2.x == 0) v.x = -1e9f;
                if (m2.y == 0) v.y = -1e9f;
                psum[mt][half] += __expf(v.x) + __expf(v.y);
                *(float2*)&S[(size_t)r * Sn + col] = v;
            }
        }
    }
    // reduce expsum across q lanes, accumulate per-row into smem then gmem
    #pragma unroll
    for (int mt = 0; mt < 4; mt++) {
        #pragma unroll
        for (int half = 0; half < 2; half++) {
            float t = psum[mt][half];
            t += __shfl_xor_sync(0xffffffffu, t, 1);
            t += __shfl_xor_sync(0xffffffffu, t, 2);
            if (q == 0)
                atomicAdd(&s_sum[wr * 64 + mt * 16 + half * 8 + grp], t);
        }
    }
    __syncthreads();
    if (tid < 128)
        atomicAdd(&rowsum[(size_t)bh * Sn + row0 + tid], s_sum[tid]);
}

// ================= attention phase C: p=exp(S)/sum, write P, ctx = P @ V ===
constexpr int PV_APL   = 128 * AST;
constexpr int PV_BPL   = 64 * AST;
constexpr int PV_STAGE = 2 * PV_APL + 2 * PV_BPL;
constexpr int PV_SMEM  = 2 * PV_STAGE * 4;

__global__ __launch_bounds__(256)
void attn_pv(float* __restrict__ Pm, const float* __restrict__ rowsum,
             const __nv_bfloat16* __restrict__ vth, const __nv_bfloat16* __restrict__ vtl,
             __nv_bfloat16* __restrict__ ctxh, __nv_bfloat16* __restrict__ ctxl)
{
    extern __shared__ uint32_t smw[];
    __shared__ float s_inv[128];
    const int tid  = threadIdx.x;
    const int wid  = tid >> 5, lane = tid & 31;
    const int grp  = lane >> 2, q = lane & 3;
    const int bh = blockIdx.y, b = bh >> 3, h = bh & 7;
    const int m0 = blockIdx.x * 128;

    float* A = Pm + (size_t)bh * Sn * Sn;
    const __nv_bfloat16* Bh_ = vth + (size_t)bh * DKn * Sn;
    const __nv_bfloat16* Bl_ = vtl + (size_t)bh * DKn * Sn;

    if (tid < 128) s_inv[tid] = 1.f / rowsum[(size_t)bh * Sn + m0 + tid];
    __syncthreads();

    float c[8][4];
    #pragma unroll
    for (int nt = 0; nt < 8; nt++)
        #pragma unroll
        for (int e = 0; e < 4; e++) c[nt][e] = 0.f;

    const int T = Sn / KC;   // 64
    float4 ra[4]; uint4 rbh, rbl;

    auto stage_A = [&](uint32_t* stg, int k0) {
        #pragma unroll
        for (int it = 0; it < 4; it++) {
            int idx = tid + it * 256;
            int r = idx >> 3, f = idx & 7;
            float4 v = ra[it];
            float inv = s_inv[r];
            v.x = __expf(v.x) * inv; v.y = __expf(v.y) * inv;
            v.z = __expf(v.z) * inv; v.w = __expf(v.w) * inv;
            *(float4*)&A[(size_t)(m0 + r) * Sn + k0 + f * 4] = v;   // final attn
            int w = r * AST + f * 2;
            uint32_t h0, h1, l0, l1;
            split2(v.x, v.y, h0, l0);
            split2(v.z, v.w, h1, l1);
            stg[w] = h0; stg[w + 1] = h1;
            stg[PV_APL + w] = l0; stg[PV_APL + w + 1] = l1;
        }
        int r = tid >> 2, f = tid & 3;
        int w = r * AST + f * 4;
        *(uint4*)&stg[2 * PV_APL + w] = rbh;
        *(uint4*)&stg[2 * PV_APL + PV_BPL + w] = rbl;
    };
    auto ldg_AB = [&](int k0) {
        #pragma unroll
        for (int it = 0; it < 4; it++) {
            int idx = tid + it * 256;
            int r = idx >> 3, f = idx & 7;
            ra[it] = *(const float4*)&A[(size_t)(m0 + r) * Sn + k0 + f * 4];
        }
        int r = tid >> 2, f = tid & 3;
        rbh = *(const uint4*)&Bh_[(size_t)r * Sn + k0 + f * 8];
        rbl = *(const uint4*)&Bl_[(size_t)r * Sn + k0 + f * 8];
    };

    ldg_AB(0);
    stage_A(smw, 0);
    __syncthreads();

    for (int i = 0; i < T; i++) {
        const uint32_t* stg = smw + (i & 1) * PV_STAGE;
        const uint32_t* Ah = stg;
        const uint32_t* Al = stg + PV_APL;
        const uint32_t* Bhp = stg + 2 * PV_APL;
        const uint32_t* Blp = stg + 2 * PV_APL + PV_BPL;

        if (i + 1 < T) ldg_AB((i + 1) * KC);

        #pragma unroll
        for (int k16 = 0; k16 < 2; k16++) {
            int arb = (wid * 16 + grp) * AST + k16 * 8 + q;
            uint32_t ah[4], al[4];
            ah[0] = Ah[arb];     ah[1] = Ah[arb + 160];
            ah[2] = Ah[arb + 4]; ah[3] = Ah[arb + 164];
            al[0] = Al[arb];     al[1] = Al[arb + 160];
            al[2] = Al[arb + 4]; al[3] = Al[arb + 164];
            #pragma unroll
            for (int nt = 0; nt < 8; nt++) {
                int brb = (nt * 8 + grp) * AST + k16 * 8 + q;
                uint32_t bh2[2], bl2[2];
                bh2[0] = Bhp[brb]; bh2[1] = Bhp[brb + 4];
                bl2[0] = Blp[brb]; bl2[1] = Blp[brb + 4];
                mma_bf16(c[nt], ah, bh2);
                mma_bf16(c[nt], ah, bl2);
                mma_bf16(c[nt], al, bh2);
            }
        }
        __syncthreads();
        if (i + 1 < T) {
            stage_A(smw + ((i + 1) & 1) * PV_STAGE, (i + 1) * KC);
            __syncthreads();
        }
    }

    #pragma unroll
    for (int nt = 0; nt < 8; nt++) {
        int col = h * DKn + nt * 8 + 2 * q;
        int r0  = m0 + wid * 16 + grp;
        uint32_t hw, lw;
        split2(c[nt][0], c[nt][1], hw, lw);
        *(uint32_t*)&ctxh[(size_t)(b * Sn + r0) * Dn + col] = hw;
        *(uint32_t*)&ctxl[(size_t)(b * Sn + r0) * Dn + col] = lw;
        split2(c[nt][2], c[nt][3], hw, lw);
        *(uint32_t*)&ctxh[(size_t)(b * Sn + r0 + 8) * Dn + col] = hw;
        *(uint32_t*)&ctxl[(size_t)(b * Sn + r0 + 8) * Dn + col] = lw;
    }
}

// ============================ small utility kernels ========================
__global__ __launch_bounds__(256)
void zero_f32(float* __restrict__ p, int n)
{
    int i = blockIdx.x * 256 + threadIdx.x;
    if (i < n) p[i] = 0.f;
}

// int32 mask -> uint8 mask (0/1)
__global__ __launch_bounds__(256)
void mask_to_u8(const int* __restrict__ m, unsigned char* __restrict__ m8, int n4)
{
    int i = blockIdx.x * 256 + threadIdx.x;
    if (i >= n4) return;
    int4 v = ((const int4*)m)[i];
    uchar4 o;
    o.x = v.x != 0; o.y = v.y != 0; o.z = v.z != 0; o.w = v.w != 0;
    ((uchar4*)m8)[i] = o;
}

// fp32 -> bf16 hi/lo planes (contiguous)
__global__ __launch_bounds__(256)
void split_planes(const float* __restrict__ src, __nv_bfloat16* __restrict__ h,
                  __nv_bfloat16* __restrict__ l, int n4)
{
    int i = blockIdx.x * 256 + threadIdx.x;
    if (i >= n4) return;
    float4 v = ((const float4*)src)[i];
    uint32_t h0, l0, h1, l1;
    split2(v.x, v.y, h0, l0);
    split2(v.z, v.w, h1, l1);
    ((uint2*)h)[i] = make_uint2(h0, h1);
    ((uint2*)l)[i] = make_uint2(l0, l1);
}

// W[K,N] -> Wt[N,K] bf16 hi/lo planes
__global__ __launch_bounds__(256)
void transpose_w(const float* __restrict__ W, __nv_bfloat16* __restrict__ Wth,
                 __nv_bfloat16* __restrict__ Wtl, int K, int N)
{
    __shared__ float t[32][33];
    int x = blockIdx.x * 32 + threadIdx.x;
    #pragma unroll
    for (int j = 0; j < 4; j++)
        t[threadIdx.y + j * 8][threadIdx.x] =
            W[(size_t)(blockIdx.y * 32 + threadIdx.y + j * 8) * N + x];
    __syncthreads();
    int x2 = blockIdx.y * 32 + threadIdx.x;
    #pragma unroll
    for (int j = 0; j < 4; j++) {
        float v = t[threadIdx.x][threadIdx.y + j * 8];
        __nv_bfloat16 hi = __float2bfloat16_rn(v);
        size_t o = (size_t)(blockIdx.x * 32 + threadIdx.y + j * 8) * K + x2;
        Wth[o] = hi;
        Wtl[o] = __float2bfloat16_rn(v - __bfloat162float(hi));
    }
}

// V slice of qkv planes -> vt[bh][64][Sn] bf16 hi/lo
__global__ __launch_bounds__(256)
void transpose_v(const __nv_bfloat16* __restrict__ qh, const __nv_bfloat16* __restrict__ ql,
                 __nv_bfloat16* __restrict__ vth, __nv_bfloat16* __restrict__ vtl)
{
    __shared__ float t[32][33];
    const int bh = blockIdx.z, b = bh >> 3, h = bh & 7;
    const int s0 = blockIdx.x * 32;
    const int d0 = blockIdx.y * 32;
    const int vcol = 2 * Dn + h * DKn;
    #pragma unroll
    for (int j = 0; j < 4; j++) {
        size_t o = (size_t)(b * Sn + s0 + threadIdx.y + j * 8) * QKVN + vcol + d0 + threadIdx.x;
        t[threadIdx.y + j * 8][threadIdx.x] =
            __bfloat162float(qh[o]) + __bfloat162float(ql[o]);
    }
    __syncthreads();
    #pragma unroll
    for (int j = 0; j < 4; j++) {
        float v = t[threadIdx.x][threadIdx.y + j * 8];
        __nv_bfloat16 hi = __float2bfloat16_rn(v);
        size_t o = ((size_t)bh * DKn + d0 + threadIdx.y + j * 8) * Sn + s0 + threadIdx.x;
        vth[o] = hi;
        vtl[o] = __float2bfloat16_rn(v - __bfloat162float(hi));
    }
}

// ---------------------------------------------------------------------------
// out = LayerNorm(a + r) * g + b   (+ optional bf16 hi/lo planes of out)
// ---------------------------------------------------------------------------
__global__ __launch_bounds__(256)
void add_ln(const float* __restrict__ a, const float* __restrict__ r,
            const float* __restrict__ g, const float* __restrict__ be,
            float* __restrict__ out, __nv_bfloat16* __restrict__ oh,
            __nv_bfloat16* __restrict__ ol)
{
    const int row = blockIdx.x, tid = threadIdx.x;
    const float* ap = a + (size_t)row * Dn;
    const float* rp = r + (size_t)row * Dn;
    float v0 = ap[tid]       + rp[tid];
    float v1 = ap[tid + 256] + rp[tid + 256];

    __shared__ float red[8];
    __shared__ float s_mu, s_inv;
    const int w = tid >> 5, lane = tid & 31;

    float s = v0 + v1;
    #pragma unroll
    for (int o = 16; o > 0; o >>= 1) s += __shfl_xor_sync(0xffffffffu, s, o);
    if (lane == 0) red[w] = s;
    __syncthreads();
    if (tid < 32) {
        float t = (tid < 8) ? red[tid] : 0.f;
        #pragma unroll
        for (int o = 4; o > 0; o >>= 1) t += __shfl_xor_sync(0xffffffffu, t, o);
        if (tid == 0) s_mu = t * (1.f / Dn);
    }
    __syncthreads();
    float mu = s_mu;
    float d0 = v0 - mu, d1 = v1 - mu;

    float qv = d0*d0 + d1*d1;
    #pragma unroll
    for (int o = 16; o > 0; o >>= 1) qv += __shfl_xor_sync(0xffffffffu, qv, o);
    __syncthreads();
    if (lane == 0) red[w] = qv;
    __syncthreads();
    if (tid < 32) {
        float t = (tid < 8) ? red[tid] : 0.f;
        #pragma unroll
        for (int o = 4; o > 0; o >>= 1) t += __shfl_xor_sync(0xffffffffu, t, o);
        if (tid == 0) s_inv = rsqrtf(t * (1.f / Dn) + 1e-6f);
    }
    __syncthreads();
    float inv = s_inv;
    float o0 = d0 * inv * g[tid]       + be[tid];
    float o1 = d1 * inv * g[tid + 256] + be[tid + 256];
    float* op = out + (size_t)row * Dn;
    op[tid]       = o0;
    op[tid + 256] = o1;
    if (oh) {
        __nv_bfloat16 h0 = __float2bfloat16_rn(o0);
        __nv_bfloat16 h1 = __float2bfloat16_rn(o1);
        size_t base = (size_t)row * Dn;
        oh[base + tid]       = h0;
        oh[base + tid + 256] = h1;
        ol[base + tid]       = __float2bfloat16_rn(o0 - __bfloat162float(h0));
        ol[base + tid + 256] = __float2bfloat16_rn(o1 - __bfloat162float(h1));
    }
}

// ---------------------------------------------------------------------------
extern "C" void kernel_launch(void* const* d_in, const int* in_sizes, int n_in,
                              void* d_out, int out_size)
{
    const float* x    = (const float*)d_in[0];
    const float* sw   = (const float*)d_in[1];
    const int*   mask = (const int*)  d_in[2];
    const float* Wq   = (const float*)d_in[3];
    const float* Wk   = (const float*)d_in[4];
    const float* Wv   = (const float*)d_in[5];
    const float* Wo   = (const float*)d_in[6];
    const float* bo   = (const float*)d_in[7];
    const float* sa   = (const float*)d_in[8];
    const float* tb   = (const float*)d_in[9];
    const float* ln1g = (const float*)d_in[10];
    const float* ln1b = (const float*)d_in[11];
    const float* ln2g = (const float*)d_in[12];
    const float* ln2b = (const float*)d_in[13];
    const float* W1   = (const float*)d_in[14];
    const float* b1   = (const float*)d_in[15];
    const float* W2   = (const float*)d_in[16];
    const float* b2   = (const float*)d_in[17];

    float* out_x2   = (float*)d_out;
    float* out_attn = (float*)d_out + (size_t)BSn * Dn;

    float *x1, *t2, *rowsum;
    unsigned char* mask8;
    __nv_bfloat16 *xh, *xl, *qkvh, *qkvl, *ctxh, *ctxl, *x1h, *x1l, *ffh, *ffl;
    __nv_bfloat16 *wqkv_h, *wqkv_l, *wo_h, *wo_l, *w1_h, *w1_l, *w2_h, *w2_l, *vth, *vtl;
    cudaGetSymbolAddress((void**)&x1,     g_x1);
    cudaGetSymbolAddress((void**)&t2,     g_t2);
    cudaGetSymbolAddress((void**)&rowsum, g_rowsum);
    cudaGetSymbolAddress((void**)&mask8,  g_mask8);
    cudaGetSymbolAddress((void**)&xh,     g_x_h);
    cudaGetSymbolAddress((void**)&xl,     g_x_l);
    cudaGetSymbolAddress((void**)&qkvh,   g_qkv_h);
    cudaGetSymbolAddress((void**)&qkvl,   g_qkv_l);
    cudaGetSymbolAddress((void**)&ctxh,   g_ctx_h);
    cudaGetSymbolAddress((void**)&ctxl,   g_ctx_l);
    cudaGetSymbolAddress((void**)&x1h,    g_x1_h);
    cudaGetSymbolAddress((void**)&x1l,    g_x1_l);
    cudaGetSymbolAddress((void**)&ffh,    g_ff_h);
    cudaGetSymbolAddress((void**)&ffl,    g_ff_l);
    cudaGetSymbolAddress((void**)&wqkv_h, g_wqkv_h);
    cudaGetSymbolAddress((void**)&wqkv_l, g_wqkv_l);
    cudaGetSymbolAddress((void**)&wo_h,   g_wo_h);
    cudaGetSymbolAddress((void**)&wo_l,   g_wo_l);
    cudaGetSymbolAddress((void**)&w1_h,   g_w1_h);
    cudaGetSymbolAddress((void**)&w1_l,   g_w1_l);
    cudaGetSymbolAddress((void**)&w2_h,   g_w2_h);
    cudaGetSymbolAddress((void**)&w2_l,   g_w2_l);
    cudaGetSymbolAddress((void**)&vth,    g_vt_h);
    cudaGetSymbolAddress((void**)&vtl,    g_vt_l);

    cudaFuncSetAttribute(gemm_mma<0,false,true>, cudaFuncAttributeMaxDynamicSharedMemorySize, GEMM_SMEM);
    cudaFuncSetAttribute(gemm_mma<1,true,false>, cudaFuncAttributeMaxDynamicSharedMemorySize, GEMM_SMEM);
    cudaFuncSetAttribute(gemm_mma<2,false,true>, cudaFuncAttributeMaxDynamicSharedMemorySize, GEMM_SMEM);
    cudaFuncSetAttribute(attn_score, cudaFuncAttributeMaxDynamicSharedMemorySize, GEMM_SMEM);
    cudaFuncSetAttribute(attn_pv,    cudaFuncAttributeMaxDynamicSharedMemorySize, PV_SMEM);

    dim3 tb8(32, 8);
    dim3 blk(256);

    // weight transposes + input split + mask compress
    transpose_w<<<dim3(Dn/32,  Dn/32),  tb8>>>(Wq, wqkv_h,            wqkv_l,            Dn, Dn);
    transpose_w<<<dim3(Dn/32,  Dn/32),  tb8>>>(Wk, wqkv_h + Dn*Dn,    wqkv_l + Dn*Dn,    Dn, Dn);
    transpose_w<<<dim3(Dn/32,  Dn/32),  tb8>>>(Wv, wqkv_h + 2*Dn*Dn,  wqkv_l + 2*Dn*Dn,  Dn, Dn);
    transpose_w<<<dim3(Dn/32,  Dn/32),  tb8>>>(Wo, wo_h, wo_l, Dn, Dn);
    transpose_w<<<dim3(DFFn/32, Dn/32), tb8>>>(W1, w1_h, w1_l, Dn, DFFn);
    transpose_w<<<dim3(Dn/32, DFFn/32), tb8>>>(W2, w2_h, w2_l, DFFn, Dn);
    split_planes<<<(BSn*Dn/4 + 255)/256, blk>>>(x, xh, xl, BSn*Dn/4);
    zero_f32<<<(BHn*Sn + 255)/256, blk>>>(rowsum, BHn*Sn);
    mask_to_u8<<<(Sn*Sn/4 + 255)/256, blk>>>(mask, mask8, Sn*Sn/4);

    // fused QKV projection -> planes
    gemm_mma<0,false,true><<<dim3(QKVN/128, BSn/128), blk, GEMM_SMEM>>>(
        xh, xl, wqkv_h, wqkv_l, nullptr, nullptr, qkvh, qkvl, BSn, QKVN, Dn);

    // V transpose for PV phase
    transpose_v<<<dim3(Sn/32, DKn/32, BHn), tb8>>>(qkvh, qkvl, vth, vtl);

    // attention: raw scores + expsums -> normalize-in-pv (writes final attn)
    attn_score<<<dim3(Sn/128, Sn/128, BHn), blk, GEMM_SMEM>>>(
        qkvh, qkvl, sw, mask8, sa, tb, out_attn, rowsum);
    attn_pv<<<dim3(Sn/128, BHn), blk, PV_SMEM>>>(
        out_attn, rowsum, vth, vtl, ctxh, ctxl);

    // output projection + bias
    gemm_mma<1,true,false><<<dim3(Dn/128, BSn/128), blk, GEMM_SMEM>>>(
        ctxh, ctxl, wo_h, wo_l, bo, t2, nullptr, nullptr, BSn, Dn, Dn);
    add_ln<<<BSn, blk>>>(x, t2, ln1g, ln1b, x1, x1h, x1l);

    // FFN
    gemm_mma<2,false,true><<<dim3(DFFn/128, BSn/128), blk, GEMM_SMEM>>>(
        x1h, x1l, w1_h, w1_l, b1, nullptr, ffh, ffl, BSn, DFFn, Dn);
    gemm_mma<1,true,false><<<dim3(Dn/128, BSn/128), blk, GEMM_SMEM>>>(
        ffh, ffl, w2_h, w2_l, b2, t2, nullptr, nullptr, BSn, Dn, DFFn);

    add_ln<<<BSn, blk>>>(x1, t2, ln2g, ln2b, out_x2, nullptr, nullptr);
}

// round 17
// speedup vs baseline: 1.5366x; 1.0998x over previous
#include <cuda_runtime.h>
#include <cuda_bf16.h>
#include <math.h>
#include <stdint.h>
#include <stddef.h>

// Problem dims (fixed by reference)
constexpr int Bn  = 2;
constexpr int Sn  = 2048;
constexpr int Dn  = 512;
constexpr int Hn  = 8;
constexpr int DKn = 64;
constexpr int DFFn= 2048;
constexpr int BSn = Bn * Sn;          // 4096 token rows
constexpr int QKVN = 3 * Dn;          // 1536 fused qkv width
constexpr int BHn = Bn * Hn;          // 16 batched heads

// ---------------- scratch (device globals; no allocation allowed) ----------
__device__ float g_x1  [BSn * Dn];
__device__ float g_t2  [BSn * Dn];
__device__ float g_rowsum[BHn * Sn];
__device__ unsigned char g_mask8[(size_t)Sn * Sn];
// activation bf16 planes (lo planes only where 3-term split is needed)
__device__ __nv_bfloat16 g_x_h  [BSn * Dn],   g_x_l  [BSn * Dn];
__device__ __nv_bfloat16 g_qkv_h[BSn * QKVN], g_qkv_l[BSn * QKVN]; // lo used for Q,K cols only
__device__ __nv_bfloat16 g_ctx_h[BSn * Dn];
__device__ __nv_bfloat16 g_x1_h [BSn * Dn],   g_x1_l [BSn * Dn];
__device__ __nv_bfloat16 g_ff_h [BSn * DFFn], g_ff_l [BSn * DFFn];
// weight bf16 planes (K-major, [N,K])
__device__ __nv_bfloat16 g_wqkv_h[QKVN * Dn], g_wqkv_l[QKVN * Dn];
__device__ __nv_bfloat16 g_wo_h  [Dn * Dn];
__device__ __nv_bfloat16 g_w1_h  [DFFn * Dn], g_w1_l  [DFFn * Dn];
__device__ __nv_bfloat16 g_w2_h  [Dn * DFFn], g_w2_l  [Dn * DFFn];
// V transposed per (b,h): [bh][64][Sn] bf16 (single)
__device__ __nv_bfloat16 g_vt_h[BHn * DKn * Sn];

// ============================ PTX helpers ==================================
__device__ __forceinline__ uint32_t smem_u32(const void* p) {
    uint32_t a;
    asm("{ .reg .u64 t; cvta.to.shared.u64 t, %1; cvt.u32.u64 %0, t; }"
        : "=r"(a) : "l"(p));
    return a;
}
__device__ __forceinline__ void mma_bf16(float* c, const uint32_t* a, const uint32_t* b) {
    asm volatile("mma.sync.aligned.m16n8k16.row.col.f32.bf16.bf16.f32 "
        "{%0,%1,%2,%3}, {%4,%5,%6,%7}, {%8,%9}, {%0,%1,%2,%3};"
        : "+f"(c[0]), "+f"(c[1]), "+f"(c[2]), "+f"(c[3])
        : "r"(a[0]), "r"(a[1]), "r"(a[2]), "r"(a[3]), "r"(b[0]), "r"(b[1]));
}
__device__ __forceinline__ uint32_t pk(__nv_bfloat16 a, __nv_bfloat16 b) {
    return (uint32_t)__bfloat16_as_ushort(a) | ((uint32_t)__bfloat16_as_ushort(b) << 16);
}
__device__ __forceinline__ uint32_t pk2f(float a, float b) {
    return pk(__float2bfloat16_rn(a), __float2bfloat16_rn(b));
}
__device__ __forceinline__ void split2(float x, float y, uint32_t& hw, uint32_t& lw) {
    __nv_bfloat16 h0 = __float2bfloat16_rn(x);
    __nv_bfloat16 h1 = __float2bfloat16_rn(y);
    hw = pk(h0, h1);
    lw = pk(__float2bfloat16_rn(x - __bfloat162float(h0)),
            __float2bfloat16_rn(y - __bfloat162float(h1)));
}
__device__ __forceinline__ void cpa16(uint32_t dst, const void* src) {
    asm volatile("cp.async.cg.shared.global [%0], [%1], 16;" :: "r"(dst), "l"(src));
}
__device__ __forceinline__ void cpa_commit() {
    asm volatile("cp.async.commit_group;" ::: "memory");
}
template<int N> __device__ __forceinline__ void cpa_wait() {
    asm volatile("cp.async.wait_group %0;" :: "n"(N) : "memory");
}

// ================= shared tiling constants =================================
constexpr int KC      = 32;
constexpr int AST     = 20;                   // padded b32 words per 32-elt row
constexpr int PLANE_W = 128 * AST;            // 2560 words
constexpr int GEMM_SMEM3 = 2 * 4 * PLANE_W * 4;   // 81920 B
constexpr int GEMM_SMEM1 = 2 * 2 * PLANE_W * 4;   // 40960 B

// ================= dense GEMM: bf16 planes, cp.async double buffer =========
// C = A @ Bt^T. 128x128 CTA tile, 8 warps of 64x32, KC=32.
// S3: 3-term hi/lo split.  EPI: 0 none, 1 +bias, 2 +bias+gelu.
// OM: 0 fp32 C, 1 single bf16 plane, 2 hi/lo planes.  ldc: C row stride.
template<int EPI, int OM, bool S3>
__global__ __launch_bounds__(256)
void gemm_mma(const __nv_bfloat16* __restrict__ Ah_, const __nv_bfloat16* __restrict__ Al_,
              const __nv_bfloat16* __restrict__ Bth, const __nv_bfloat16* __restrict__ Btl,
              const float* __restrict__ bias, float* __restrict__ Cf,
              __nv_bfloat16* __restrict__ Ch, __nv_bfloat16* __restrict__ Cl,
              int K, int ldc)
{
    constexpr int SW = (S3 ? 4 : 2) * PLANE_W;
    extern __shared__ uint32_t smw[];
    const uint32_t sbase = smem_u32(smw);
    const int tid  = threadIdx.x;
    const int wid  = tid >> 5, lane = tid & 31;
    const int grp  = lane >> 2, q = lane & 3;
    const int wr   = wid >> 2, wc = wid & 3;
    const int row0 = blockIdx.y * 128;
    const int col0 = blockIdx.x * 128;

    float c[4][4][4];
    #pragma unroll
    for (int mt = 0; mt < 4; mt++)
        #pragma unroll
        for (int nt = 0; nt < 4; nt++)
            #pragma unroll
            for (int e = 0; e < 4; e++) c[mt][nt][e] = 0.f;

    const int T = K / KC;

    auto issue = [&](int i) {
        int k0 = i * KC;
        uint32_t sb = sbase + (uint32_t)((i & 1) * SW) * 4;
        #pragma unroll
        for (int it = 0; it < (S3 ? 8 : 4); it++) {
            int idx = tid + it * 256;
            int plane = idx >> 9, rem = idx & 511;
            int r = rem >> 2, ch = rem & 3;
            const __nv_bfloat16* src;
            if constexpr (S3) {
                if (plane == 0)      src = Ah_ + (size_t)(row0 + r) * K + k0 + ch * 8;
                else if (plane == 1) src = Al_ + (size_t)(row0 + r) * K + k0 + ch * 8;
                else if (plane == 2) src = Bth + (size_t)(col0 + r) * K + k0 + ch * 8;
                else                 src = Btl + (size_t)(col0 + r) * K + k0 + ch * 8;
            } else {
                src = (plane == 0) ? Ah_ + (size_t)(row0 + r) * K + k0 + ch * 8
                                   : Bth + (size_t)(col0 + r) * K + k0 + ch * 8;
            }
            cpa16(sb + (uint32_t)(plane * PLANE_W + r * AST + ch * 4) * 4, src);
        }
        cpa_commit();
    };

    issue(0);
    for (int i = 0; i < T; i++) {
        if (i + 1 < T) { issue(i + 1); cpa_wait<1>(); }
        else           { cpa_wait<0>(); }
        __syncthreads();

        const uint32_t* stg = smw + (i & 1) * SW;
        const uint32_t* Ah = stg;
        const uint32_t* Al = stg + PLANE_W;                     // S3 only
        const uint32_t* Bh = stg + (S3 ? 2 : 1) * PLANE_W;
        const uint32_t* Bl = stg + 3 * PLANE_W;                 // S3 only
        #pragma unroll
        for (int k16 = 0; k16 < 2; k16++) {
            uint32_t bh[4][2], bl[4][2];
            #pragma unroll
            for (int nt = 0; nt < 4; nt++) {
                int brb = (wc * 32 + nt * 8 + grp) * AST + k16 * 8 + q;
                bh[nt][0] = Bh[brb]; bh[nt][1] = Bh[brb + 4];
                if constexpr (S3) { bl[nt][0] = Bl[brb]; bl[nt][1] = Bl[brb + 4]; }
            }
            #pragma unroll
            for (int mt = 0; mt < 4; mt++) {
                int arb = (wr * 64 + mt * 16 + grp) * AST + k16 * 8 + q;
                uint32_t ah[4], al[4];
                ah[0] = Ah[arb];     ah[1] = Ah[arb + 160];
                ah[2] = Ah[arb + 4]; ah[3] = Ah[arb + 164];
                if constexpr (S3) {
                    al[0] = Al[arb];     al[1] = Al[arb + 160];
                    al[2] = Al[arb + 4]; al[3] = Al[arb + 164];
                }
                #pragma unroll
                for (int nt = 0; nt < 4; nt++) {
                    mma_bf16(c[mt][nt], ah, bh[nt]);
                    if constexpr (S3) {
                        mma_bf16(c[mt][nt], ah, bl[nt]);
                        mma_bf16(c[mt][nt], al, bh[nt]);
                    }
                }
            }
        }
        __syncthreads();
    }

    #pragma unroll
    for (int mt = 0; mt < 4; mt++) {
        #pragma unroll
        for (int nt = 0; nt < 4; nt++) {
            int col = col0 + wc * 32 + nt * 8 + 2 * q;
            int r0  = row0 + wr * 64 + mt * 16 + grp;
            float2 v0 = make_float2(c[mt][nt][0], c[mt][nt][1]);
            float2 v1 = make_float2(c[mt][nt][2], c[mt][nt][3]);
            if (EPI >= 1) {
                float b0 = bias[col], b1 = bias[col + 1];
                v0.x += b0; v0.y += b1; v1.x += b0; v1.y += b1;
            }
            if (EPI == 2) {
                v0.x = 0.5f * v0.x * (1.0f + erff(v0.x * 0.70710678118654752f));
                v0.y = 0.5f * v0.y * (1.0f + erff(v0.y * 0.70710678118654752f));
                v1.x = 0.5f * v1.x * (1.0f + erff(v1.x * 0.70710678118654752f));
                v1.y = 0.5f * v1.y * (1.0f + erff(v1.y * 0.70710678118654752f));
            }
            if constexpr (OM == 0) {
                *(float2*)&Cf[(size_t)r0 * ldc + col]       = v0;
                *(float2*)&Cf[(size_t)(r0 + 8) * ldc + col] = v1;
            } else if constexpr (OM == 1) {
                *(uint32_t*)&Ch[(size_t)r0 * ldc + col]       = pk2f(v0.x, v0.y);
                *(uint32_t*)&Ch[(size_t)(r0 + 8) * ldc + col] = pk2f(v1.x, v1.y);
            } else {
                uint32_t hw, lw;
                split2(v0.x, v0.y, hw, lw);
                *(uint32_t*)&Ch[(size_t)r0 * ldc + col] = hw;
                *(uint32_t*)&Cl[(size_t)r0 * ldc + col] = lw;
                split2(v1.x, v1.y, hw, lw);
                *(uint32_t*)&Ch[(size_t)(r0 + 8) * ldc + col] = hw;
                *(uint32_t*)&Cl[(size_t)(r0 + 8) * ldc + col] = lw;
            }
        }
    }
}

// ================= attention phase A: S = Q K^T /8 + bias, mask, expsum ====
// 3-term split (protects P precision). Stages both K-chunks (K=64).
constexpr int SC_STAGE_W = 4 * PLANE_W;
__global__ __launch_bounds__(256)
void attn_score(const __nv_bfloat16* __restrict__ qh, const __nv_bfloat16* __restrict__ ql,
                const float* __restrict__ sw, const unsigned char* __restrict__ mask8,
                const float* __restrict__ sa, const float* __restrict__ tb,
                float* __restrict__ S_out, float* __restrict__ rowsum)
{
    extern __shared__ uint32_t smw[];
    __shared__ float s_rb[128];
    __shared__ float s_sum[128];
    const uint32_t sbase = smem_u32(smw);
    const int tid  = threadIdx.x;
    const int wid  = tid >> 5, lane = tid & 31;
    const int grp  = lane >> 2, q = lane & 3;
    const int wr   = wid >> 2, wc = wid & 3;
    const int bh = blockIdx.z, b = bh >> 3, h = bh & 7;
    const int row0 = blockIdx.y * 128;
    const int col0 = blockIdx.x * 128;

    const size_t qbase = (size_t)b * Sn * QKVN + h * DKn;        // Q cols
    const size_t kbase = (size_t)b * Sn * QKVN + Dn + h * DKn;   // K cols

    #pragma unroll
    for (int s = 0; s < 2; s++) {
        int k0 = s * KC;
        uint32_t sb = sbase + (uint32_t)(s * SC_STAGE_W) * 4;
        #pragma unroll
        for (int it = 0; it < 8; it++) {
            int idx = tid + it * 256;
            int plane = idx >> 9, rem = idx & 511;
            int r = rem >> 2, ch = rem & 3;
            const __nv_bfloat16* src;
            if (plane == 0)      src = qh + qbase + (size_t)(row0 + r) * QKVN + k0 + ch * 8;
            else if (plane == 1) src = ql + qbase + (size_t)(row0 + r) * QKVN + k0 + ch * 8;
            else if (plane == 2) src = qh + kbase + (size_t)(col0 + r) * QKVN + k0 + ch * 8;
            else                 src = ql + kbase + (size_t)(col0 + r) * QKVN + k0 + ch * 8;
            cpa16(sb + (uint32_t)(plane * PLANE_W + r * AST + ch * 4) * 4, src);
        }
    }
    cpa_commit();

    if (tid < 128) {
        int row = row0 + tid;
        const float* swp = sw + ((size_t)b * Sn + row) * 4;
        const float* sap = sa + h * 4;
        s_rb[tid] = tb[h] + sap[0]*swp[0] + sap[1]*swp[1]
                          + sap[2]*swp[2] + sap[3]*swp[3];
        s_sum[tid] = 0.f;
    }

    float c[4][4][4];
    #pragma unroll
    for (int mt = 0; mt < 4; mt++)
        #pragma unroll
        for (int nt = 0; nt < 4; nt++)
            #pragma unroll
            for (int e = 0; e < 4; e++) c[mt][nt][e] = 0.f;

    cpa_wait<0>();
    __syncthreads();

    #pragma unroll
    for (int s = 0; s < 2; s++) {
        const uint32_t* stg = smw + s * SC_STAGE_W;
        const uint32_t* Ah = stg;
        const uint32_t* Al = stg + PLANE_W;
        const uint32_t* Bh = stg + 2 * PLANE_W;
        const uint32_t* Bl = stg + 3 * PLANE_W;
        #pragma unroll
        for (int k16 = 0; k16 < 2; k16++) {
            uint32_t bh2[4][2], bl2[4][2];
            #pragma unroll
            for (int nt = 0; nt < 4; nt++) {
                int brb = (wc * 32 + nt * 8 + grp) * AST + k16 * 8 + q;
                bh2[nt][0] = Bh[brb]; bh2[nt][1] = Bh[brb + 4];
                bl2[nt][0] = Bl[brb]; bl2[nt][1] = Bl[brb + 4];
            }
            #pragma unroll
            for (int mt = 0; mt < 4; mt++) {
                int arb = (wr * 64 + mt * 16 + grp) * AST + k16 * 8 + q;
                uint32_t ah[4], al[4];
                ah[0] = Ah[arb];     ah[1] = Ah[arb + 160];
                ah[2] = Ah[arb + 4]; ah[3] = Ah[arb + 164];
                al[0] = Al[arb];     al[1] = Al[arb + 160];
                al[2] = Al[arb + 4]; al[3] = Al[arb + 164];
                #pragma unroll
                for (int nt = 0; nt < 4; nt++) {
                    mma_bf16(c[mt][nt], ah, bh2[nt]);
                    mma_bf16(c[mt][nt], ah, bl2[nt]);
                    mma_bf16(c[mt][nt], al, bh2[nt]);
                }
            }
        }
    }

    float* S = S_out + (size_t)bh * Sn * Sn;
    float psum[4][2];
    #pragma unroll
    for (int mt = 0; mt < 4; mt++) { psum[mt][0] = 0.f; psum[mt][1] = 0.f; }

    #pragma unroll
    for (int mt = 0; mt < 4; mt++) {
        #pragma unroll
        for (int nt = 0; nt < 4; nt++) {
            int col = col0 + wc * 32 + nt * 8 + 2 * q;
            int r0  = row0 + wr * 64 + mt * 16 + grp;
            #pragma unroll
            for (int half = 0; half < 2; half++) {
                int r = r0 + half * 8;
                float2 v = make_float2(c[mt][nt][2*half], c[mt][nt][2*half + 1]);
                float rb = s_rb[r - row0];
                v.x = v.x * 0.125f + rb;
                v.y = v.y * 0.125f + rb;
                uchar2 m2 = *(const uchar2*)&mask8[(size_t)r * Sn + col];
                if (m2.x == 0) v.x = -1e9f;
                if (m2.y == 0) v.y = -1e9f;
                psum[mt][half] += __expf(v.x) + __expf(v.y);
                *(float2*)&S[(size_t)r * Sn + col] = v;
            }
        }
    }
    #pragma unroll
    for (int mt = 0; mt < 4; mt++) {
        #pragma unroll
        for (int half = 0; half < 2; half++) {
            float t = psum[mt][half];
            t += __shfl_xor_sync(0xffffffffu, t, 1);
            t += __shfl_xor_sync(0xffffffffu, t, 2);
            if (q == 0)
                atomicAdd(&s_sum[wr * 64 + mt * 16 + half * 8 + grp], t);
        }
    }
    __syncthreads();
    if (tid < 128)
        atomicAdd(&rowsum[(size_t)bh * Sn + row0 + tid], s_sum[tid]);
}

// ================= attention phase C: p=exp(S)/sum, write P, ctx = P @ V ===
// Single-bf16 (errors diluted through the 2%-magnitude attention branch).
constexpr int PV_APL   = 128 * AST;
constexpr int PV_BPL   = 64 * AST;
constexpr int PV_STAGE = PV_APL + PV_BPL;     // 3840 words
constexpr int PV_SMEM  = 2 * PV_STAGE * 4;    // 30720 B

__global__ __launch_bounds__(256)
void attn_pv(float* __restrict__ Pm, const float* __restrict__ rowsum,
             const __nv_bfloat16* __restrict__ vth, __nv_bfloat16* __restrict__ ctxh)
{
    extern __shared__ uint32_t smw[];
    __shared__ float s_inv[128];
    const int tid  = threadIdx.x;
    const int wid  = tid >> 5, lane = tid & 31;
    const int grp  = lane >> 2, q = lane & 3;
    const int bh = blockIdx.y, b = bh >> 3, h = bh & 7;
    const int m0 = blockIdx.x * 128;

    float* A = Pm + (size_t)bh * Sn * Sn;
    const __nv_bfloat16* Bh_ = vth + (size_t)bh * DKn * Sn;

    if (tid < 128) s_inv[tid] = 1.f / rowsum[(size_t)bh * Sn + m0 + tid];
    __syncthreads();

    float c[8][4];
    #pragma unroll
    for (int nt = 0; nt < 8; nt++)
        #pragma unroll
        for (int e = 0; e < 4; e++) c[nt][e] = 0.f;

    const int T = Sn / KC;   // 64
    float4 ra[4]; uint4 rbh;

    auto stage_A = [&](uint32_t* stg, int k0) {
        #pragma unroll
        for (int it = 0; it < 4; it++) {
            int idx = tid + it * 256;
            int r = idx >> 3, f = idx & 7;
            float4 v = ra[it];
            float inv = s_inv[r];
            v.x = __expf(v.x) * inv; v.y = __expf(v.y) * inv;
            v.z = __expf(v.z) * inv; v.w = __expf(v.w) * inv;
            *(float4*)&A[(size_t)(m0 + r) * Sn + k0 + f * 4] = v;   // final attn
            int w = r * AST + f * 2;
            stg[w]     = pk2f(v.x, v.y);
            stg[w + 1] = pk2f(v.z, v.w);
        }
        int r = tid >> 2, f = tid & 3;
        *(uint4*)&stg[PV_APL + r * AST + f * 4] = rbh;
    };
    auto ldg_AB = [&](int k0) {
        #pragma unroll
        for (int it = 0; it < 4; it++) {
            int idx = tid + it * 256;
            int r = idx >> 3, f = idx & 7;
            ra[it] = *(const float4*)&A[(size_t)(m0 + r) * Sn + k0 + f * 4];
        }
        int r = tid >> 2, f = tid & 3;
        rbh = *(const uint4*)&Bh_[(size_t)r * Sn + k0 + f * 8];
    };

    ldg_AB(0);
    stage_A(smw, 0);
    __syncthreads();

    for (int i = 0; i < T; i++) {
        const uint32_t* stg = smw + (i & 1) * PV_STAGE;
        const uint32_t* Ah = stg;
        const uint32_t* Bhp = stg + PV_APL;

        if (i + 1 < T) ldg_AB((i + 1) * KC);

        #pragma unroll
        for (int k16 = 0; k16 < 2; k16++) {
            int arb = (wid * 16 + grp) * AST + k16 * 8 + q;
            uint32_t ah[4];
            ah[0] = Ah[arb];     ah[1] = Ah[arb + 160];
            ah[2] = Ah[arb + 4]; ah[3] = Ah[arb + 164];
            #pragma unroll
            for (int nt = 0; nt < 8; nt++) {
                int brb = (nt * 8 + grp) * AST + k16 * 8 + q;
                uint32_t bh2[2];
                bh2[0] = Bhp[brb]; bh2[1] = Bhp[brb + 4];
                mma_bf16(c[nt], ah, bh2);
            }
        }
        __syncthreads();
        if (i + 1 < T) {
            stage_A(smw + ((i + 1) & 1) * PV_STAGE, (i + 1) * KC);
            __syncthreads();
        }
    }

    #pragma unroll
    for (int nt = 0; nt < 8; nt++) {
        int col = h * DKn + nt * 8 + 2 * q;
        int r0  = m0 + wid * 16 + grp;
        *(uint32_t*)&ctxh[(size_t)(b * Sn + r0) * Dn + col]     = pk2f(c[nt][0], c[nt][1]);
        *(uint32_t*)&ctxh[(size_t)(b * Sn + r0 + 8) * Dn + col] = pk2f(c[nt][2], c[nt][3]);
    }
}

// ============================ small utility kernels ========================
__global__ __launch_bounds__(256)
void zero_f32(float* __restrict__ p, int n)
{
    int i = blockIdx.x * 256 + threadIdx.x;
    if (i < n) p[i] = 0.f;
}

__global__ __launch_bounds__(256)
void mask_to_u8(const int* __restrict__ m, unsigned char* __restrict__ m8, int n4)
{
    int i = blockIdx.x * 256 + threadIdx.x;
    if (i >= n4) return;
    int4 v = ((const int4*)m)[i];
    uchar4 o;
    o.x = v.x != 0; o.y = v.y != 0; o.z = v.z != 0; o.w = v.w != 0;
    ((uchar4*)m8)[i] = o;
}

__global__ __launch_bounds__(256)
void split_planes(const float* __restrict__ src, __nv_bfloat16* __restrict__ h,
                  __nv_bfloat16* __restrict__ l, int n4)
{
    int i = blockIdx.x * 256 + threadIdx.x;
    if (i >= n4) return;
    float4 v = ((const float4*)src)[i];
    uint32_t h0, l0, h1, l1;
    split2(v.x, v.y, h0, l0);
    split2(v.z, v.w, h1, l1);
    ((uint2*)h)[i] = make_uint2(h0, h1);
    ((uint2*)l)[i] = make_uint2(l0, l1);
}

// batched Wq/Wk/Wv transpose -> hi/lo planes [1536,512]
__global__ __launch_bounds__(256)
void transpose_w3(const float* __restrict__ W0, const float* __restrict__ W1p,
                  const float* __restrict__ W2p, __nv_bfloat16* __restrict__ Wth,
                  __nv_bfloat16* __restrict__ Wtl)
{
    __shared__ float t[32][33];
    const int z = blockIdx.z;
    const float* W = (z == 0) ? W0 : (z == 1) ? W1p : W2p;
    const size_t obase = (size_t)z * Dn * Dn;
    int x = blockIdx.x * 32 + threadIdx.x;
    #pragma unroll
    for (int j = 0; j < 4; j++)
        t[threadIdx.y + j * 8][threadIdx.x] =
            W[(size_t)(blockIdx.y * 32 + threadIdx.y + j * 8) * Dn + x];
    __syncthreads();
    int x2 = blockIdx.y * 32 + threadIdx.x;
    #pragma unroll
    for (int j = 0; j < 4; j++) {
        float v = t[threadIdx.x][threadIdx.y + j * 8];
        __nv_bfloat16 hi = __float2bfloat16_rn(v);
        size_t o = obase + (size_t)(blockIdx.x * 32 + threadIdx.y + j * 8) * Dn + x2;
        Wth[o] = hi;
        Wtl[o] = __float2bfloat16_rn(v - __bfloat162float(hi));
    }
}

// generic W[K,N] -> Wt[N,K] hi/lo planes
__global__ __launch_bounds__(256)
void transpose_w(const float* __restrict__ W, __nv_bfloat16* __restrict__ Wth,
                 __nv_bfloat16* __restrict__ Wtl, int K, int N)
{
    __shared__ float t[32][33];
    int x = blockIdx.x * 32 + threadIdx.x;
    #pragma unroll
    for (int j = 0; j < 4; j++)
        t[threadIdx.y + j * 8][threadIdx.x] =
            W[(size_t)(blockIdx.y * 32 + threadIdx.y + j * 8) * N + x];
    __syncthreads();
    int x2 = blockIdx.y * 32 + threadIdx.x;
    #pragma unroll
    for (int j = 0; j < 4; j++) {
        float v = t[threadIdx.x][threadIdx.y + j * 8];
        __nv_bfloat16 hi = __float2bfloat16_rn(v);
        size_t o = (size_t)(blockIdx.x * 32 + threadIdx.y + j * 8) * K + x2;
        Wth[o] = hi;
        Wtl[o] = __float2bfloat16_rn(v - __bfloat162float(hi));
    }
}

// W[K,N] -> Wt[N,K] single bf16 plane (Wo)
__global__ __launch_bounds__(256)
void transpose_w1(const float* __restrict__ W, __nv_bfloat16* __restrict__ Wth,
                  int K, int N)
{
    __shared__ float t[32][33];
    int x = blockIdx.x * 32 + threadIdx.x;
    #pragma unroll
    for (int j = 0; j < 4; j++)
        t[threadIdx.y + j * 8][threadIdx.x] =
            W[(size_t)(blockIdx.y * 32 + threadIdx.y + j * 8) * N + x];
    __syncthreads();
    int x2 = blockIdx.y * 32 + threadIdx.x;
    #pragma unroll
    for (int j = 0; j < 4; j++) {
        float v = t[threadIdx.x][threadIdx.y + j * 8];
        Wth[(size_t)(blockIdx.x * 32 + threadIdx.y + j * 8) * K + x2] =
            __float2bfloat16_rn(v);
    }
}

// V slice of qkv (single plane) -> vt[bh][64][Sn], pure bf16 bit transpose
__global__ __launch_bounds__(256)
void transpose_v(const __nv_bfloat16* __restrict__ qh, __nv_bfloat16* __restrict__ vth)
{
    __shared__ unsigned short t[32][33];
    const int bh = blockIdx.z, b = bh >> 3, h = bh & 7;
    const int s0 = blockIdx.x * 32;
    const int d0 = blockIdx.y * 32;
    const int vcol = 2 * Dn + h * DKn;
    #pragma unroll
    for (int j = 0; j < 4; j++) {
        size_t o = (size_t)(b * Sn + s0 + threadIdx.y + j * 8) * QKVN + vcol + d0 + threadIdx.x;
        t[threadIdx.y + j * 8][threadIdx.x] = __bfloat16_as_ushort(qh[o]);
    }
    __syncthreads();
    #pragma unroll
    for (int j = 0; j < 4; j++) {
        size_t o = ((size_t)bh * DKn + d0 + threadIdx.y + j * 8) * Sn + s0 + threadIdx.x;
        vth[o] = __ushort_as_bfloat16(t[threadIdx.x][threadIdx.y + j * 8]);
    }
}

// ---------------------------------------------------------------------------
// out = LayerNorm(a + r) * g + b   (+ optional bf16 hi/lo planes of out)
// ---------------------------------------------------------------------------
__global__ __launch_bounds__(256)
void add_ln(const float* __restrict__ a, const float* __restrict__ r,
            const float* __restrict__ g, const float* __restrict__ be,
            float* __restrict__ out, __nv_bfloat16* __restrict__ oh,
            __nv_bfloat16* __restrict__ ol)
{
    const int row = blockIdx.x, tid = threadIdx.x;
    const float* ap = a + (size_t)row * Dn;
    const float* rp = r + (size_t)row * Dn;
    float v0 = ap[tid]       + rp[tid];
    float v1 = ap[tid + 256] + rp[tid + 256];

    __shared__ float red[8];
    __shared__ float s_mu, s_inv;
    const int w = tid >> 5, lane = tid & 31;

    float s = v0 + v1;
    #pragma unroll
    for (int o = 16; o > 0; o >>= 1) s += __shfl_xor_sync(0xffffffffu, s, o);
    if (lane == 0) red[w] = s;
    __syncthreads();
    if (tid < 32) {
        float t = (tid < 8) ? red[tid] : 0.f;
        #pragma unroll
        for (int o = 4; o > 0; o >>= 1) t += __shfl_xor_sync(0xffffffffu, t, o);
        if (tid == 0) s_mu = t * (1.f / Dn);
    }
    __syncthreads();
    float mu = s_mu;
    float d0 = v0 - mu, d1 = v1 - mu;

    float qv = d0*d0 + d1*d1;
    #pragma unroll
    for (int o = 16; o > 0; o >>= 1) qv += __shfl_xor_sync(0xffffffffu, qv, o);
    __syncthreads();
    if (lane == 0) red[w] = qv;
    __syncthreads();
    if (tid < 32) {
        float t = (tid < 8) ? red[tid] : 0.f;
        #pragma unroll
        for (int o = 4; o > 0; o >>= 1) t += __shfl_xor_sync(0xffffffffu, t, o);
        if (tid == 0) s_inv = rsqrtf(t * (1.f / Dn) + 1e-6f);
    }
    __syncthreads();
    float inv = s_inv;
    float o0 = d0 * inv * g[tid]       + be[tid];
    float o1 = d1 * inv * g[tid + 256] + be[tid + 256];
    float* op = out + (size_t)row * Dn;
    op[tid]       = o0;
    op[tid + 256] = o1;
    if (oh) {
        __nv_bfloat16 h0 = __float2bfloat16_rn(o0);
        __nv_bfloat16 h1 = __float2bfloat16_rn(o1);
        size_t base = (size_t)row * Dn;
        oh[base + tid]       = h0;
        oh[base + tid + 256] = h1;
        ol[base + tid]       = __float2bfloat16_rn(o0 - __bfloat162float(h0));
        ol[base + tid + 256] = __float2bfloat16_rn(o1 - __bfloat162float(h1));
    }
}

// ---------------------------------------------------------------------------
extern "C" void kernel_launch(void* const* d_in, const int* in_sizes, int n_in,
                              void* d_out, int out_size)
{
    const float* x    = (const float*)d_in[0];
    const float* sw   = (const float*)d_in[1];
    const int*   mask = (const int*)  d_in[2];
    const float* Wq   = (const float*)d_in[3];
    const float* Wk   = (const float*)d_in[4];
    const float* Wv   = (const float*)d_in[5];
    const float* Wo   = (const float*)d_in[6];
    const float* bo   = (const float*)d_in[7];
    const float* sa   = (const float*)d_in[8];
    const float* tb   = (const float*)d_in[9];
    const float* ln1g = (const float*)d_in[10];
    const float* ln1b = (const float*)d_in[11];
    const float* ln2g = (const float*)d_in[12];
    const float* ln2b = (const float*)d_in[13];
    const float* W1   = (const float*)d_in[14];
    const float* b1   = (const float*)d_in[15];
    const float* W2   = (const float*)d_in[16];
    const float* b2   = (const float*)d_in[17];

    float* out_x2   = (float*)d_out;
    float* out_attn = (float*)d_out + (size_t)BSn * Dn;

    float *x1, *t2, *rowsum;
    unsigned char* mask8;
    __nv_bfloat16 *xh, *xl, *qkvh, *qkvl, *ctxh, *x1h, *x1l, *ffh, *ffl;
    __nv_bfloat16 *wqkv_h, *wqkv_l, *wo_h, *w1_h, *w1_l, *w2_h, *w2_l, *vth;
    cudaGetSymbolAddress((void**)&x1,     g_x1);
    cudaGetSymbolAddress((void**)&t2,     g_t2);
    cudaGetSymbolAddress((void**)&rowsum, g_rowsum);
    cudaGetSymbolAddress((void**)&mask8,  g_mask8);
    cudaGetSymbolAddress((void**)&xh,     g_x_h);
    cudaGetSymbolAddress((void**)&xl,     g_x_l);
    cudaGetSymbolAddress((void**)&qkvh,   g_qkv_h);
    cudaGetSymbolAddress((void**)&qkvl,   g_qkv_l);
    cudaGetSymbolAddress((void**)&ctxh,   g_ctx_h);
    cudaGetSymbolAddress((void**)&x1h,    g_x1_h);
    cudaGetSymbolAddress((void**)&x1l,    g_x1_l);
    cudaGetSymbolAddress((void**)&ffh,    g_ff_h);
    cudaGetSymbolAddress((void**)&ffl,    g_ff_l);
    cudaGetSymbolAddress((void**)&wqkv_h, g_wqkv_h);
    cudaGetSymbolAddress((void**)&wqkv_l, g_wqkv_l);
    cudaGetSymbolAddress((void**)&wo_h,   g_wo_h);
    cudaGetSymbolAddress((void**)&w1_h,   g_w1_h);
    cudaGetSymbolAddress((void**)&w1_l,   g_w1_l);
    cudaGetSymbolAddress((void**)&w2_h,   g_w2_h);
    cudaGetSymbolAddress((void**)&w2_l,   g_w2_l);
    cudaGetSymbolAddress((void**)&vth,    g_vt_h);

    cudaFuncSetAttribute(gemm_mma<0,2,true>,  cudaFuncAttributeMaxDynamicSharedMemorySize, GEMM_SMEM3);
    cudaFuncSetAttribute(gemm_mma<2,2,true>,  cudaFuncAttributeMaxDynamicSharedMemorySize, GEMM_SMEM3);
    cudaFuncSetAttribute(gemm_mma<1,0,true>,  cudaFuncAttributeMaxDynamicSharedMemorySize, GEMM_SMEM3);
    cudaFuncSetAttribute(gemm_mma<0,1,false>, cudaFuncAttributeMaxDynamicSharedMemorySize, GEMM_SMEM1);
    cudaFuncSetAttribute(gemm_mma<1,0,false>, cudaFuncAttributeMaxDynamicSharedMemorySize, GEMM_SMEM1);
    cudaFuncSetAttribute(attn_score, cudaFuncAttributeMaxDynamicSharedMemorySize, GEMM_SMEM3);
    cudaFuncSetAttribute(attn_pv,    cudaFuncAttributeMaxDynamicSharedMemorySize, PV_SMEM);

    dim3 tb8(32, 8);
    dim3 blk(256);

    // launch order places attn_score at index 5 (ncu -s 5 -c 1 capture target)
    transpose_w3<<<dim3(Dn/32, Dn/32, 3), tb8>>>(Wq, Wk, Wv, wqkv_h, wqkv_l);       // 0
    split_planes<<<(BSn*Dn/4 + 255)/256, blk>>>(x, xh, xl, BSn*Dn/4);               // 1
    mask_to_u8<<<(Sn*Sn/4 + 255)/256, blk>>>(mask, mask8, Sn*Sn/4);                 // 2
    zero_f32<<<(BHn*Sn + 255)/256, blk>>>(rowsum, BHn*Sn);                          // 3

    // Q,K projection (3-term) -> hi/lo planes, cols [0,1024)
    gemm_mma<0,2,true><<<dim3(1024/128, BSn/128), blk, GEMM_SMEM3>>>(               // 4
        xh, xl, wqkv_h, wqkv_l, nullptr, nullptr, qkvh, qkvl, Dn, QKVN);

    // attention scores (3-term) + expsums                                          // 5
    attn_score<<<dim3(Sn/128, Sn/128, BHn), blk, GEMM_SMEM3>>>(
        qkvh, qkvl, sw, mask8, sa, tb, out_attn, rowsum);

    // V projection (single) -> single plane, cols [1024,1536)
    gemm_mma<0,1,false><<<dim3(Dn/128, BSn/128), blk, GEMM_SMEM1>>>(                // 6
        xh, nullptr, wqkv_h + (size_t)2*Dn*Dn, nullptr, nullptr, nullptr,
        qkvh + 2*Dn, nullptr, Dn, QKVN);

    transpose_v<<<dim3(Sn/32, DKn/32, BHn), tb8>>>(qkvh, vth);                      // 7

    // normalize + write P + ctx = P@V (single)
    attn_pv<<<dim3(Sn/128, BHn), blk, PV_SMEM>>>(out_attn, rowsum, vth, ctxh);      // 8

    transpose_w1<<<dim3(Dn/32, Dn/32), tb8>>>(Wo, wo_h, Dn, Dn);                    // 9

    // output projection (single) + bias
    gemm_mma<1,0,false><<<dim3(Dn/128, BSn/128), blk, GEMM_SMEM1>>>(                // 10
        ctxh, nullptr, wo_h, nullptr, bo, t2, nullptr, nullptr, Dn, Dn);
    add_ln<<<BSn, blk>>>(x, t2, ln1g, ln1b, x1, x1h, x1l);                          // 11

    transpose_w<<<dim3(DFFn/32, Dn/32), tb8>>>(W1, w1_h, w1_l, Dn, DFFn);           // 12
    transpose_w<<<dim3(Dn/32, DFFn/32), tb8>>>(W2, w2_h, w2_l, DFFn, Dn);           // 13

    // FFN (3-term)
    gemm_mma<2,2,true><<<dim3(DFFn/128, BSn/128), blk, GEMM_SMEM3>>>(               // 14
        x1h, x1l, w1_h, w1_l, b1, nullptr, ffh, ffl, Dn, DFFn);
    gemm_mma<1,0,true><<<dim3(Dn/128, BSn/128), blk, GEMM_SMEM3>>>(                 // 15
        ffh, ffl, w2_h, w2_l, b2, t2, nullptr, nullptr, DFFn, Dn);

    add_ln<<<BSn, blk>>>(x1, t2, ln2g, ln2b, out_x2, nullptr, nullptr);             // 16
}